// round 1
// baseline (speedup 1.0000x reference)
#include <cuda_runtime.h>
#include <math.h>

// Problem dims
#define T1 63            // decode steps (T-1)
#define BB 32            // batch
#define HH 512           // hidden
#define VV 32000         // vocab
#define MR (T1*BB)       // 2016 rows
#define GD (4*HH)        // 2048 gates

// Scratch (device globals; no allocation allowed)
__device__ float g_gx[(size_t)MR * GD];     // (t*32+b, 2048) input-gate contributions + biases
__device__ float g_hs[(size_t)MR * HH];     // all hidden states, row = t*32+b
__device__ float g_hbuf[2][BB * HH];        // double-buffered h
__device__ float g_c[BB * HH];              // cell state

// ---------------------------------------------------------------------------
// init: zero h0 / c0 (must run every launch; graph replays reuse the globals)
// ---------------------------------------------------------------------------
__global__ void init_kernel() {
    int i = blockIdx.x * blockDim.x + threadIdx.x;
    if (i < BB * HH) { g_hbuf[0][i] = 0.f; g_c[i] = 0.f; }
}

// ---------------------------------------------------------------------------
// SGEMM 1: g_gx[m][n] = sum_k xs[m][k] * W_ih[n][k] + b_ih[n] + b_hh[n]
//   xs row m=(t*32+b): k<512 -> enc[b][k], else emb[captions[b][t]][k-512]
//   M=2016, N=2048, K=1024. 128x128x16 tiles, 256 thr, 8x8/thread.
// ---------------------------------------------------------------------------
__global__ __launch_bounds__(256, 2) void gemm_gx(
    const float* __restrict__ enc, const int* __restrict__ cap,
    const float* __restrict__ emb, const float* __restrict__ W,
    const float* __restrict__ bih, const float* __restrict__ bhh)
{
    __shared__ float As[16][132];
    __shared__ float Bs[16][132];
    const int tid = threadIdx.x;
    const int m0 = blockIdx.y * 128, n0 = blockIdx.x * 128;
    const int lr = tid >> 2, lc = (tid & 3) << 2;   // loader: row, k-col (x4)
    const int tr = (tid >> 4) << 3, tc = (tid & 15) << 3;

    float acc[8][8];
#pragma unroll
    for (int i = 0; i < 8; i++)
#pragma unroll
        for (int j = 0; j < 8; j++) acc[i][j] = 0.f;

    for (int k0 = 0; k0 < 1024; k0 += 16) {
#pragma unroll
        for (int i = 0; i < 2; i++) {
            int row = m0 + lr + i * 64;
            float4 v = make_float4(0.f, 0.f, 0.f, 0.f);
            if (row < MR) {
                int tt = row >> 5, b = row & 31;
                int k = k0 + lc;
                const float* src = (k < 512)
                    ? (enc + b * 512 + k)
                    : (emb + (size_t)cap[b * 64 + tt] * 512 + (k - 512));
                v = *(const float4*)src;
            }
            As[lc + 0][lr + i * 64] = v.x;
            As[lc + 1][lr + i * 64] = v.y;
            As[lc + 2][lr + i * 64] = v.z;
            As[lc + 3][lr + i * 64] = v.w;
        }
#pragma unroll
        for (int i = 0; i < 2; i++) {
            int n = n0 + lr + i * 64;
            float4 v = *(const float4*)(W + (size_t)n * 1024 + k0 + lc);
            Bs[lc + 0][lr + i * 64] = v.x;
            Bs[lc + 1][lr + i * 64] = v.y;
            Bs[lc + 2][lr + i * 64] = v.z;
            Bs[lc + 3][lr + i * 64] = v.w;
        }
        __syncthreads();
#pragma unroll
        for (int kk = 0; kk < 16; kk++) {
            float a[8], bf[8];
            *(float4*)(a)     = *(float4*)&As[kk][tr];
            *(float4*)(a + 4) = *(float4*)&As[kk][tr + 4];
            *(float4*)(bf)     = *(float4*)&Bs[kk][tc];
            *(float4*)(bf + 4) = *(float4*)&Bs[kk][tc + 4];
#pragma unroll
            for (int i = 0; i < 8; i++)
#pragma unroll
                for (int j = 0; j < 8; j++) acc[i][j] += a[i] * bf[j];
        }
        __syncthreads();
    }
#pragma unroll
    for (int i = 0; i < 8; i++) {
        int row = m0 + tr + i;
        if (row < MR) {
#pragma unroll
            for (int j = 0; j < 8; j++) {
                int col = n0 + tc + j;
                g_gx[(size_t)row * GD + col] = acc[i][j] + bih[col] + bhh[col];
            }
        }
    }
}

// ---------------------------------------------------------------------------
// LSTM step t: gates[b][g*512+j] = g_gx[t][b][...] + h_{t-1}[b] . W_hh[g*512+j]
// 128 CTAs x 256 thr. CTA owns 4 j-columns (all 4 gates, all 32 b).
// thread = (kh in {0,1} K-half, b, jj). W_hh rows staged in smem (padded).
// ---------------------------------------------------------------------------
__global__ __launch_bounds__(256) void lstm_step(const float* __restrict__ Whh, int t)
{
    __shared__ float sW[16 * 516];
    __shared__ float sRed[128 * 4];
    const int tid = threadIdx.x;
    const int j0 = blockIdx.x * 4;
    const int kh = tid >> 7, r = tid & 127;
    const int b = r >> 2, jj = r & 3;

    // stage the 16 needed W_hh rows: row index = g*4 + jj
#pragma unroll
    for (int i = 0; i < 8; i++) {
        int idx = tid + i * 256;           // float4 units, 0..2047
        int row = idx >> 7, c4 = idx & 127;
        int g = row >> 2, j = row & 3;
        float4 v = *(const float4*)(Whh + (size_t)(g * 512 + j0 + j) * 512 + c4 * 4);
        *(float4*)&sW[row * 516 + c4 * 4] = v;
    }
    __syncthreads();

    const float* hin = g_hbuf[t & 1] + b * 512;
    float a0 = 0.f, a1 = 0.f, a2 = 0.f, a3 = 0.f;
    const int kb = kh * 64;
#pragma unroll 8
    for (int k4 = 0; k4 < 64; k4++) {
        float4 hv = *(const float4*)(hin + (kb + k4) * 4);
        float4 w0 = *(const float4*)&sW[(0 * 4 + jj) * 516 + (kb + k4) * 4];
        float4 w1 = *(const float4*)&sW[(1 * 4 + jj) * 516 + (kb + k4) * 4];
        float4 w2 = *(const float4*)&sW[(2 * 4 + jj) * 516 + (kb + k4) * 4];
        float4 w3 = *(const float4*)&sW[(3 * 4 + jj) * 516 + (kb + k4) * 4];
        a0 += hv.x * w0.x + hv.y * w0.y + hv.z * w0.z + hv.w * w0.w;
        a1 += hv.x * w1.x + hv.y * w1.y + hv.z * w1.z + hv.w * w1.w;
        a2 += hv.x * w2.x + hv.y * w2.y + hv.z * w2.z + hv.w * w2.w;
        a3 += hv.x * w3.x + hv.y * w3.y + hv.z * w3.z + hv.w * w3.w;
    }
    if (kh == 1) {
        sRed[r * 4 + 0] = a0; sRed[r * 4 + 1] = a1;
        sRed[r * 4 + 2] = a2; sRed[r * 4 + 3] = a3;
    }
    __syncthreads();
    if (kh == 0) {
        const int j = j0 + jj;
        const size_t gxb = ((size_t)t * 32 + b) * GD + j;
        float gi = a0 + sRed[r * 4 + 0] + g_gx[gxb + 0 * 512];
        float gf = a1 + sRed[r * 4 + 1] + g_gx[gxb + 1 * 512];
        float gg = a2 + sRed[r * 4 + 2] + g_gx[gxb + 2 * 512];
        float go = a3 + sRed[r * 4 + 3] + g_gx[gxb + 3 * 512];
        float si = 1.f / (1.f + expf(-gi));
        float sf = 1.f / (1.f + expf(-gf));
        float tg = tanhf(gg);
        float so = 1.f / (1.f + expf(-go));
        float c = sf * g_c[b * 512 + j] + si * tg;
        g_c[b * 512 + j] = c;
        float h = so * tanhf(c);
        g_hbuf[(t + 1) & 1][b * 512 + j] = h;
        g_hs[((size_t)t * 32 + b) * 512 + j] = h;
    }
}

// ---------------------------------------------------------------------------
// SGEMM 2: logits[b][t][v] = g_hs[m] . W_out[v] + b_out[v]   (m = t*32+b)
//   M=2016, N=32000, K=512.
// ---------------------------------------------------------------------------
__global__ __launch_bounds__(256, 2) void gemm_logits(
    const float* __restrict__ W, const float* __restrict__ bias,
    float* __restrict__ out)
{
    __shared__ float As[16][132];
    __shared__ float Bs[16][132];
    const int tid = threadIdx.x;
    const int m0 = blockIdx.y * 128, n0 = blockIdx.x * 128;
    const int lr = tid >> 2, lc = (tid & 3) << 2;
    const int tr = (tid >> 4) << 3, tc = (tid & 15) << 3;

    float acc[8][8];
#pragma unroll
    for (int i = 0; i < 8; i++)
#pragma unroll
        for (int j = 0; j < 8; j++) acc[i][j] = 0.f;

    for (int k0 = 0; k0 < 512; k0 += 16) {
#pragma unroll
        for (int i = 0; i < 2; i++) {
            int row = m0 + lr + i * 64;
            float4 v = make_float4(0.f, 0.f, 0.f, 0.f);
            if (row < MR) v = *(const float4*)(g_hs + (size_t)row * 512 + k0 + lc);
            As[lc + 0][lr + i * 64] = v.x;
            As[lc + 1][lr + i * 64] = v.y;
            As[lc + 2][lr + i * 64] = v.z;
            As[lc + 3][lr + i * 64] = v.w;
        }
#pragma unroll
        for (int i = 0; i < 2; i++) {
            int n = n0 + lr + i * 64;
            float4 v = *(const float4*)(W + (size_t)n * 512 + k0 + lc);
            Bs[lc + 0][lr + i * 64] = v.x;
            Bs[lc + 1][lr + i * 64] = v.y;
            Bs[lc + 2][lr + i * 64] = v.z;
            Bs[lc + 3][lr + i * 64] = v.w;
        }
        __syncthreads();
#pragma unroll
        for (int kk = 0; kk < 16; kk++) {
            float a[8], bf[8];
            *(float4*)(a)     = *(float4*)&As[kk][tr];
            *(float4*)(a + 4) = *(float4*)&As[kk][tr + 4];
            *(float4*)(bf)     = *(float4*)&Bs[kk][tc];
            *(float4*)(bf + 4) = *(float4*)&Bs[kk][tc + 4];
#pragma unroll
            for (int i = 0; i < 8; i++)
#pragma unroll
                for (int j = 0; j < 8; j++) acc[i][j] += a[i] * bf[j];
        }
        __syncthreads();
    }
#pragma unroll
    for (int i = 0; i < 8; i++) {
        int row = m0 + tr + i;
        if (row < MR) {
            int tt = row >> 5, b = row & 31;
            float* dst = out + ((size_t)(b * 63 + tt)) * VV + n0 + tc;
#pragma unroll
            for (int j = 0; j < 8; j += 4) {
                float4 v;
                v.x = acc[i][j + 0] + bias[n0 + tc + j + 0];
                v.y = acc[i][j + 1] + bias[n0 + tc + j + 1];
                v.z = acc[i][j + 2] + bias[n0 + tc + j + 2];
                v.w = acc[i][j + 3] + bias[n0 + tc + j + 3];
                *(float4*)(dst + j) = v;
            }
        }
    }
}

// ---------------------------------------------------------------------------
// Row max + argmax (first-max tie-breaking, matching jnp.argmax)
// One CTA per output row m = b*63+t.
// ---------------------------------------------------------------------------
__global__ void rowmax_kernel(const float* __restrict__ logits,
                              float* __restrict__ probs, float* __restrict__ pred)
{
    const int m = blockIdx.x;
    const float* row = logits + (size_t)m * VV;
    float best = -INFINITY; int bi = 0;
    for (int v = threadIdx.x; v < VV; v += 256) {
        float x = row[v];
        if (x > best) { best = x; bi = v; }
    }
    __shared__ float sv[256];
    __shared__ int   si[256];
    sv[threadIdx.x] = best; si[threadIdx.x] = bi;
    __syncthreads();
    for (int s = 128; s > 0; s >>= 1) {
        if (threadIdx.x < s) {
            float o = sv[threadIdx.x + s]; int oi = si[threadIdx.x + s];
            float c = sv[threadIdx.x];     int ci = si[threadIdx.x];
            if (o > c || (o == c && oi < ci)) { sv[threadIdx.x] = o; si[threadIdx.x] = oi; }
        }
        __syncthreads();
    }
    if (threadIdx.x == 0) { probs[m] = sv[0]; pred[m] = (float)si[0]; }
}

// ---------------------------------------------------------------------------
extern "C" void kernel_launch(void* const* d_in, const int* in_sizes, int n_in,
                              void* d_out, int out_size)
{
    const float* enc  = (const float*)d_in[0];   // (32, 512)
    const int*   cap  = (const int*)  d_in[1];   // (32, 64)
    const float* emb  = (const float*)d_in[2];   // (32000, 512)
    const float* Wih  = (const float*)d_in[3];   // (2048, 1024)
    const float* Whh  = (const float*)d_in[4];   // (2048, 512)
    const float* bih  = (const float*)d_in[5];   // (2048,)
    const float* bhh  = (const float*)d_in[6];   // (2048,)
    const float* Wout = (const float*)d_in[7];   // (32000, 512)
    const float* bout = (const float*)d_in[8];   // (32000,)
    float* out = (float*)d_out;

    init_kernel<<<64, 256>>>();
    gemm_gx<<<dim3(16, 16), 256>>>(enc, cap, emb, Wih, bih, bhh);
    for (int t = 0; t < T1; t++) lstm_step<<<128, 256>>>(Whh, t);
    gemm_logits<<<dim3(250, 16), 256>>>(Wout, bout, out);

    const long logits_elems = (long)BB * T1 * VV;          // 64,512,000
    if ((long)out_size >= logits_elems + 2L * BB * T1) {
        rowmax_kernel<<<MR, 256>>>(out, out + logits_elems,
                                   out + logits_elems + (long)BB * T1);
    }
}

// round 2
// speedup vs baseline: 1.1607x; 1.1607x over previous
#include <cuda_runtime.h>
#include <math.h>

// Problem dims
#define T1 63            // decode steps (T-1)
#define BB 32            // batch
#define HH 512           // hidden
#define VV 32000         // vocab
#define MR (T1*BB)       // 2016 rows
#define GD (4*HH)        // 2048 gates

// Scratch (device globals; no allocation allowed)
__device__ float g_gx[(size_t)MR * GD];     // (t*32+b, 2048) input-gate contributions + biases
__device__ float g_hs[(size_t)MR * HH];     // all hidden states, row = t*32+b
__device__ float g_hbuf[2][BB * HH];        // double-buffered h
__device__ unsigned g_bar;                  // grid barrier counter

// smem layout sizes (floats)
#define SW_STRIDE 520    // 16 rows of 512 + pad
#define SH_STRIDE 516    // 32 rows of 512 + pad
#define SW_FLOATS (16 * SW_STRIDE)            // 8320
#define SH_FLOATS (32 * SH_STRIDE)            // 16512
#define SRED_FLOATS (8 * 32 * 4 * 4)          // 4096
#define SC_FLOATS 128
#define SMEM_FLOATS (SW_FLOATS + SH_FLOATS + SRED_FLOATS + SC_FLOATS)
#define SMEM_BYTES (SMEM_FLOATS * 4)          // 116,224 B

// ---------------------------------------------------------------------------
// init: zero grid-barrier counter (graph replays reuse the global)
// ---------------------------------------------------------------------------
__global__ void init_kernel() {
    if (threadIdx.x == 0 && blockIdx.x == 0) g_bar = 0u;
}

// ---------------------------------------------------------------------------
// SGEMM 1: g_gx[m][n] = sum_k xs[m][k] * W_ih[n][k] + b_ih[n] + b_hh[n]
// ---------------------------------------------------------------------------
__global__ __launch_bounds__(256, 2) void gemm_gx(
    const float* __restrict__ enc, const int* __restrict__ cap,
    const float* __restrict__ emb, const float* __restrict__ W,
    const float* __restrict__ bih, const float* __restrict__ bhh)
{
    __shared__ float As[16][132];
    __shared__ float Bs[16][132];
    const int tid = threadIdx.x;
    const int m0 = blockIdx.y * 128, n0 = blockIdx.x * 128;
    const int lr = tid >> 2, lc = (tid & 3) << 2;
    const int tr = (tid >> 4) << 3, tc = (tid & 15) << 3;

    float acc[8][8];
#pragma unroll
    for (int i = 0; i < 8; i++)
#pragma unroll
        for (int j = 0; j < 8; j++) acc[i][j] = 0.f;

    for (int k0 = 0; k0 < 1024; k0 += 16) {
#pragma unroll
        for (int i = 0; i < 2; i++) {
            int row = m0 + lr + i * 64;
            float4 v = make_float4(0.f, 0.f, 0.f, 0.f);
            if (row < MR) {
                int tt = row >> 5, b = row & 31;
                int k = k0 + lc;
                const float* src = (k < 512)
                    ? (enc + b * 512 + k)
                    : (emb + (size_t)cap[b * 64 + tt] * 512 + (k - 512));
                v = *(const float4*)src;
            }
            As[lc + 0][lr + i * 64] = v.x;
            As[lc + 1][lr + i * 64] = v.y;
            As[lc + 2][lr + i * 64] = v.z;
            As[lc + 3][lr + i * 64] = v.w;
        }
#pragma unroll
        for (int i = 0; i < 2; i++) {
            int n = n0 + lr + i * 64;
            float4 v = *(const float4*)(W + (size_t)n * 1024 + k0 + lc);
            Bs[lc + 0][lr + i * 64] = v.x;
            Bs[lc + 1][lr + i * 64] = v.y;
            Bs[lc + 2][lr + i * 64] = v.z;
            Bs[lc + 3][lr + i * 64] = v.w;
        }
        __syncthreads();
#pragma unroll
        for (int kk = 0; kk < 16; kk++) {
            float a[8], bf[8];
            *(float4*)(a)     = *(float4*)&As[kk][tr];
            *(float4*)(a + 4) = *(float4*)&As[kk][tr + 4];
            *(float4*)(bf)     = *(float4*)&Bs[kk][tc];
            *(float4*)(bf + 4) = *(float4*)&Bs[kk][tc + 4];
#pragma unroll
            for (int i = 0; i < 8; i++)
#pragma unroll
                for (int j = 0; j < 8; j++) acc[i][j] += a[i] * bf[j];
        }
        __syncthreads();
    }
#pragma unroll
    for (int i = 0; i < 8; i++) {
        int row = m0 + tr + i;
        if (row < MR) {
#pragma unroll
            for (int j = 0; j < 8; j++) {
                int col = n0 + tc + j;
                g_gx[(size_t)row * GD + col] = acc[i][j] + bih[col] + bhh[col];
            }
        }
    }
}

// ---------------------------------------------------------------------------
// Persistent LSTM recurrence: ONE kernel, 63 steps, grid barrier between steps.
// grid = 128 CTAs (<= 148 SMs, 1 CTA/SM via smem => co-resident), 256 threads.
// CTA owns 4 hidden columns j0..j0+3 (=> 16 gate rows of W_hh in smem, kept
// for all steps). Per step: stage h (64KB) into smem, matvec with thread
// mapping (ks=8 K-chunks) x (bq=8) x (jj=4), nb=4 batches/thread spaced by 8.
// ---------------------------------------------------------------------------
__device__ __forceinline__ void grid_barrier(unsigned target) {
    __syncthreads();
    if (threadIdx.x == 0) {
        unsigned a = atomicAdd(&g_bar, 1u) + 1u;
        if (a < target) {
            while (*(volatile unsigned*)&g_bar < target) { }
        }
    }
    __syncthreads();
}

__global__ __launch_bounds__(256, 1) void lstm_persist(const float* __restrict__ Whh)
{
    extern __shared__ float sm[];
    float* sW   = sm;                          // [16][520]
    float* sH   = sm + SW_FLOATS;              // [32][516]
    float* sRed = sH + SH_FLOATS;              // [ks=8][b=32][jj=4][g=4]
    float* sC   = sRed + SRED_FLOATS;          // [128] = (b*4 + jj)

    const int tid = threadIdx.x;
    const int j0 = blockIdx.x * 4;
    const int jj = tid & 3;
    const int bq = (tid >> 2) & 7;   // base batch 0..7; thread's b = bq + 8*ib
    const int ks = tid >> 5;         // 0..7 -> K-chunk of 64

    // Stage the 16 W_hh rows (g*512 + j0 + j) once, reused every step.
    for (int i = tid; i < 16 * 128; i += 256) {   // float4 units
        int row = i >> 7, c4 = i & 127;
        int g = row >> 2, j = row & 3;
        float4 v = *(const float4*)(Whh + (size_t)(g * 512 + j0 + j) * 512 + c4 * 4);
        *(float4*)&sW[row * SW_STRIDE + c4 * 4] = v;
    }
    if (tid < 128) sC[tid] = 0.f;
    __syncthreads();

    // ---- step 0: h = 0 -> gates = gx only ----
    if (tid < 128) {
        int b = tid >> 2, jl = tid & 3;
        int j = j0 + jl;
        size_t gxb = (size_t)b * GD + j;
        float gi = g_gx[gxb +    0];
        float gf = g_gx[gxb +  512];
        float gg = g_gx[gxb + 1024];
        float go = g_gx[gxb + 1536];
        float si = 1.f / (1.f + expf(-gi));
        float tg = tanhf(gg);
        float so = 1.f / (1.f + expf(-go));
        (void)gf;  // sigmoid(f)*c0 = 0
        float c = si * tg;
        sC[tid] = c;
        float h = so * tanhf(c);
        g_hbuf[0][b * 512 + j] = h;
        g_hs[(size_t)b * 512 + j] = h;
    }
    __threadfence();

    for (int t = 1; t < T1; t++) {
        grid_barrier(128u * (unsigned)t);

        // stage h_{t-1} into smem (L2-coherent loads)
        const float* hsrc = g_hbuf[(t - 1) & 1];
        for (int i = tid; i < 4096; i += 256) {     // float4 units (32*512/4)
            int b = i >> 7, c4 = i & 127;
            float4 v = __ldcg((const float4*)(hsrc + i * 4));
            *(float4*)&sH[b * SH_STRIDE + c4 * 4] = v;
        }
        __syncthreads();

        // matvec: acc[ib][g] over this thread's K chunk
        float acc[4][4];
#pragma unroll
        for (int ib = 0; ib < 4; ib++)
#pragma unroll
            for (int g = 0; g < 4; g++) acc[ib][g] = 0.f;

        const int kb = ks * 64;
#pragma unroll
        for (int k4 = 0; k4 < 16; k4++) {
            const int kk = kb + k4 * 4;
            float4 w0 = *(const float4*)&sW[(0 * 4 + jj) * SW_STRIDE + kk];
            float4 w1 = *(const float4*)&sW[(1 * 4 + jj) * SW_STRIDE + kk];
            float4 w2 = *(const float4*)&sW[(2 * 4 + jj) * SW_STRIDE + kk];
            float4 w3 = *(const float4*)&sW[(3 * 4 + jj) * SW_STRIDE + kk];
#pragma unroll
            for (int ib = 0; ib < 4; ib++) {
                float4 hv = *(const float4*)&sH[(bq + 8 * ib) * SH_STRIDE + kk];
                acc[ib][0] += hv.x * w0.x + hv.y * w0.y + hv.z * w0.z + hv.w * w0.w;
                acc[ib][1] += hv.x * w1.x + hv.y * w1.y + hv.z * w1.z + hv.w * w1.w;
                acc[ib][2] += hv.x * w2.x + hv.y * w2.y + hv.z * w2.z + hv.w * w2.w;
                acc[ib][3] += hv.x * w3.x + hv.y * w3.y + hv.z * w3.z + hv.w * w3.w;
            }
        }
        // partials -> sRed[ks][b][jj][g]
#pragma unroll
        for (int ib = 0; ib < 4; ib++) {
            int b = bq + 8 * ib;
            *(float4*)&sRed[((ks * 32 + b) * 4 + jj) * 4] =
                make_float4(acc[ib][0], acc[ib][1], acc[ib][2], acc[ib][3]);
        }
        __syncthreads();

        if (tid < 128) {
            int b = tid >> 2, jl = tid & 3;
            float4 s = make_float4(0.f, 0.f, 0.f, 0.f);
#pragma unroll
            for (int k = 0; k < 8; k++) {
                float4 p = *(const float4*)&sRed[((k * 32 + b) * 4 + jl) * 4];
                s.x += p.x; s.y += p.y; s.z += p.z; s.w += p.w;
            }
            int j = j0 + jl;
            size_t gxb = ((size_t)t * 32 + b) * GD + j;
            float gi = s.x + g_gx[gxb +    0];
            float gf = s.y + g_gx[gxb +  512];
            float gg = s.z + g_gx[gxb + 1024];
            float go = s.w + g_gx[gxb + 1536];
            float si = 1.f / (1.f + expf(-gi));
            float sf = 1.f / (1.f + expf(-gf));
            float tg = tanhf(gg);
            float so = 1.f / (1.f + expf(-go));
            float c = sf * sC[tid] + si * tg;
            sC[tid] = c;
            float h = so * tanhf(c);
            g_hbuf[t & 1][b * 512 + j] = h;
            g_hs[((size_t)t * 32 + b) * 512 + j] = h;
        }
        __threadfence();
    }
}

// ---------------------------------------------------------------------------
// SGEMM 2: logits[b][t][v] = g_hs[m] . W_out[v] + b_out[v]   (m = t*32+b)
// ---------------------------------------------------------------------------
__global__ __launch_bounds__(256, 2) void gemm_logits(
    const float* __restrict__ W, const float* __restrict__ bias,
    float* __restrict__ out)
{
    __shared__ float As[16][132];
    __shared__ float Bs[16][132];
    const int tid = threadIdx.x;
    const int m0 = blockIdx.y * 128, n0 = blockIdx.x * 128;
    const int lr = tid >> 2, lc = (tid & 3) << 2;
    const int tr = (tid >> 4) << 3, tc = (tid & 15) << 3;

    float acc[8][8];
#pragma unroll
    for (int i = 0; i < 8; i++)
#pragma unroll
        for (int j = 0; j < 8; j++) acc[i][j] = 0.f;

    for (int k0 = 0; k0 < 512; k0 += 16) {
#pragma unroll
        for (int i = 0; i < 2; i++) {
            int row = m0 + lr + i * 64;
            float4 v = make_float4(0.f, 0.f, 0.f, 0.f);
            if (row < MR) v = *(const float4*)(g_hs + (size_t)row * 512 + k0 + lc);
            As[lc + 0][lr + i * 64] = v.x;
            As[lc + 1][lr + i * 64] = v.y;
            As[lc + 2][lr + i * 64] = v.z;
            As[lc + 3][lr + i * 64] = v.w;
        }
#pragma unroll
        for (int i = 0; i < 2; i++) {
            int n = n0 + lr + i * 64;
            float4 v = *(const float4*)(W + (size_t)n * 512 + k0 + lc);
            Bs[lc + 0][lr + i * 64] = v.x;
            Bs[lc + 1][lr + i * 64] = v.y;
            Bs[lc + 2][lr + i * 64] = v.z;
            Bs[lc + 3][lr + i * 64] = v.w;
        }
        __syncthreads();
#pragma unroll
        for (int kk = 0; kk < 16; kk++) {
            float a[8], bf[8];
            *(float4*)(a)     = *(float4*)&As[kk][tr];
            *(float4*)(a + 4) = *(float4*)&As[kk][tr + 4];
            *(float4*)(bf)     = *(float4*)&Bs[kk][tc];
            *(float4*)(bf + 4) = *(float4*)&Bs[kk][tc + 4];
#pragma unroll
            for (int i = 0; i < 8; i++)
#pragma unroll
                for (int j = 0; j < 8; j++) acc[i][j] += a[i] * bf[j];
        }
        __syncthreads();
    }
#pragma unroll
    for (int i = 0; i < 8; i++) {
        int row = m0 + tr + i;
        if (row < MR) {
            int tt = row >> 5, b = row & 31;
            float* dst = out + ((size_t)(b * 63 + tt)) * VV + n0 + tc;
#pragma unroll
            for (int j = 0; j < 8; j += 4) {
                float4 v;
                v.x = acc[i][j + 0] + bias[n0 + tc + j + 0];
                v.y = acc[i][j + 1] + bias[n0 + tc + j + 1];
                v.z = acc[i][j + 2] + bias[n0 + tc + j + 2];
                v.w = acc[i][j + 3] + bias[n0 + tc + j + 3];
                *(float4*)(dst + j) = v;
            }
        }
    }
}

// ---------------------------------------------------------------------------
// Row max + argmax (first-max tie-breaking, matching jnp.argmax)
// ---------------------------------------------------------------------------
__global__ void rowmax_kernel(const float* __restrict__ logits,
                              float* __restrict__ probs, float* __restrict__ pred)
{
    const int m = blockIdx.x;
    const float* row = logits + (size_t)m * VV;
    float best = -INFINITY; int bi = 0;
    for (int v = threadIdx.x; v < VV; v += 256) {
        float x = row[v];
        if (x > best) { best = x; bi = v; }
    }
    __shared__ float sv[256];
    __shared__ int   si[256];
    sv[threadIdx.x] = best; si[threadIdx.x] = bi;
    __syncthreads();
    for (int s = 128; s > 0; s >>= 1) {
        if (threadIdx.x < s) {
            float o = sv[threadIdx.x + s]; int oi = si[threadIdx.x + s];
            float c = sv[threadIdx.x];     int ci = si[threadIdx.x];
            if (o > c || (o == c && oi < ci)) { sv[threadIdx.x] = o; si[threadIdx.x] = oi; }
        }
        __syncthreads();
    }
    if (threadIdx.x == 0) { probs[m] = sv[0]; pred[m] = (float)si[0]; }
}

// ---------------------------------------------------------------------------
extern "C" void kernel_launch(void* const* d_in, const int* in_sizes, int n_in,
                              void* d_out, int out_size)
{
    const float* enc  = (const float*)d_in[0];   // (32, 512)
    const int*   cap  = (const int*)  d_in[1];   // (32, 64)
    const float* emb  = (const float*)d_in[2];   // (32000, 512)
    const float* Wih  = (const float*)d_in[3];   // (2048, 1024)
    const float* Whh  = (const float*)d_in[4];   // (2048, 512)
    const float* bih  = (const float*)d_in[5];   // (2048,)
    const float* bhh  = (const float*)d_in[6];   // (2048,)
    const float* Wout = (const float*)d_in[7];   // (32000, 512)
    const float* bout = (const float*)d_in[8];   // (32000,)
    float* out = (float*)d_out;

    cudaFuncSetAttribute(lstm_persist,
                         cudaFuncAttributeMaxDynamicSharedMemorySize, SMEM_BYTES);

    init_kernel<<<1, 32>>>();
    gemm_gx<<<dim3(16, 16), 256>>>(enc, cap, emb, Wih, bih, bhh);
    lstm_persist<<<128, 256, SMEM_BYTES>>>(Whh);
    gemm_logits<<<dim3(250, 16), 256>>>(Wout, bout, out);

    const long logits_elems = (long)BB * T1 * VV;          // 64,512,000
    if ((long)out_size >= logits_elems + 2L * BB * T1) {
        rowmax_kernel<<<MR, 256>>>(out, out + logits_elems,
                                   out + logits_elems + (long)BB * T1);
    }
}

// round 5
// speedup vs baseline: 1.9212x; 1.6552x over previous
#include <cuda_runtime.h>
#include <cuda_bf16.h>
#include <math.h>
#include <stdint.h>

// Problem dims
#define T1 63
#define BB 32
#define HH 512
#define VV 32000
#define MR (T1*BB)       // 2016
#define GD (4*HH)        // 2048

// Scratch (device globals)
__device__ float g_gx[(size_t)MR * GD];
__device__ float g_hs[(size_t)MR * HH];
__device__ float g_hbuf[2][BB * HH];
__device__ unsigned g_bar;
__device__ __nv_bfloat16 g_wbh[(size_t)VV * HH];   // W_out hi
__device__ __nv_bfloat16 g_wbl[(size_t)VV * HH];   // W_out lo
__device__ __nv_bfloat16 g_hsh[(size_t)MR * HH];   // h hi
__device__ __nv_bfloat16 g_hsl[(size_t)MR * HH];   // h lo

// ---------------- persistent-LSTM smem sizes ----------------
#define SW_STRIDE 520
#define SH_STRIDE 516
#define SW_FLOATS (16 * SW_STRIDE)
#define SH_FLOATS (32 * SH_STRIDE)
#define SRED_FLOATS (8 * 32 * 4 * 4)
#define SC_FLOATS 128
#define SMEM_FLOATS (SW_FLOATS + SH_FLOATS + SRED_FLOATS + SC_FLOATS)
#define SMEM_BYTES (SMEM_FLOATS * 4)

__device__ __forceinline__ uint32_t smem_u32(const void* p) {
    uint32_t a;
    asm("{ .reg .u64 t; cvta.to.shared.u64 t, %1; cvt.u32.u64 %0, t; }"
        : "=r"(a) : "l"(p));
    return a;
}

#define LDMX4(R, addr) \
    asm volatile("ldmatrix.sync.aligned.m8n8.x4.shared.b16 {%0,%1,%2,%3}, [%4];" \
        : "=r"((R)[0]), "=r"((R)[1]), "=r"((R)[2]), "=r"((R)[3]) : "r"(addr))

#define MMA16816(C, A, B0, B1) \
    asm volatile("mma.sync.aligned.m16n8k16.row.col.f32.bf16.bf16.f32 " \
        "{%0,%1,%2,%3}, {%4,%5,%6,%7}, {%8,%9}, {%0,%1,%2,%3};" \
        : "+f"((C)[0]), "+f"((C)[1]), "+f"((C)[2]), "+f"((C)[3]) \
        : "r"((A)[0]), "r"((A)[1]), "r"((A)[2]), "r"((A)[3]), "r"(B0), "r"(B1))

// ---------------------------------------------------------------------------
__global__ void init_kernel() {
    if (threadIdx.x == 0 && blockIdx.x == 0) g_bar = 0u;
}

// ---------------------------------------------------------------------------
// SGEMM 1 (fp32, unchanged): g_gx = xs @ W_ih^T + b_ih + b_hh
// ---------------------------------------------------------------------------
__global__ __launch_bounds__(256, 2) void gemm_gx(
    const float* __restrict__ enc, const int* __restrict__ cap,
    const float* __restrict__ emb, const float* __restrict__ W,
    const float* __restrict__ bih, const float* __restrict__ bhh)
{
    __shared__ float As[16][132];
    __shared__ float Bs[16][132];
    const int tid = threadIdx.x;
    const int m0 = blockIdx.y * 128, n0 = blockIdx.x * 128;
    const int lr = tid >> 2, lc = (tid & 3) << 2;
    const int tr = (tid >> 4) << 3, tc = (tid & 15) << 3;

    float acc[8][8];
#pragma unroll
    for (int i = 0; i < 8; i++)
#pragma unroll
        for (int j = 0; j < 8; j++) acc[i][j] = 0.f;

    for (int k0 = 0; k0 < 1024; k0 += 16) {
#pragma unroll
        for (int i = 0; i < 2; i++) {
            int row = m0 + lr + i * 64;
            float4 v = make_float4(0.f, 0.f, 0.f, 0.f);
            if (row < MR) {
                int tt = row >> 5, b = row & 31;
                int k = k0 + lc;
                const float* src = (k < 512)
                    ? (enc + b * 512 + k)
                    : (emb + (size_t)cap[b * 64 + tt] * 512 + (k - 512));
                v = *(const float4*)src;
            }
            As[lc + 0][lr + i * 64] = v.x;
            As[lc + 1][lr + i * 64] = v.y;
            As[lc + 2][lr + i * 64] = v.z;
            As[lc + 3][lr + i * 64] = v.w;
        }
#pragma unroll
        for (int i = 0; i < 2; i++) {
            int n = n0 + lr + i * 64;
            float4 v = *(const float4*)(W + (size_t)n * 1024 + k0 + lc);
            Bs[lc + 0][lr + i * 64] = v.x;
            Bs[lc + 1][lr + i * 64] = v.y;
            Bs[lc + 2][lr + i * 64] = v.z;
            Bs[lc + 3][lr + i * 64] = v.w;
        }
        __syncthreads();
#pragma unroll
        for (int kk = 0; kk < 16; kk++) {
            float a[8], bf[8];
            *(float4*)(a)     = *(float4*)&As[kk][tr];
            *(float4*)(a + 4) = *(float4*)&As[kk][tr + 4];
            *(float4*)(bf)     = *(float4*)&Bs[kk][tc];
            *(float4*)(bf + 4) = *(float4*)&Bs[kk][tc + 4];
#pragma unroll
            for (int i = 0; i < 8; i++)
#pragma unroll
                for (int j = 0; j < 8; j++) acc[i][j] += a[i] * bf[j];
        }
        __syncthreads();
    }
#pragma unroll
    for (int i = 0; i < 8; i++) {
        int row = m0 + tr + i;
        if (row < MR) {
#pragma unroll
            for (int j = 0; j < 8; j++) {
                int col = n0 + tc + j;
                g_gx[(size_t)row * GD + col] = acc[i][j] + bih[col] + bhh[col];
            }
        }
    }
}

// ---------------------------------------------------------------------------
// Persistent LSTM recurrence (unchanged)
// ---------------------------------------------------------------------------
__device__ __forceinline__ void grid_barrier(unsigned target) {
    __syncthreads();
    if (threadIdx.x == 0) {
        unsigned a = atomicAdd(&g_bar, 1u) + 1u;
        if (a < target) {
            while (*(volatile unsigned*)&g_bar < target) { }
        }
    }
    __syncthreads();
}

__global__ __launch_bounds__(256, 1) void lstm_persist(const float* __restrict__ Whh)
{
    extern __shared__ float sm[];
    float* sW   = sm;
    float* sH   = sm + SW_FLOATS;
    float* sRed = sH + SH_FLOATS;
    float* sC   = sRed + SRED_FLOATS;

    const int tid = threadIdx.x;
    const int j0 = blockIdx.x * 4;
    const int jj = tid & 3;
    const int bq = (tid >> 2) & 7;
    const int ks = tid >> 5;

    for (int i = tid; i < 16 * 128; i += 256) {
        int row = i >> 7, c4 = i & 127;
        int g = row >> 2, j = row & 3;
        float4 v = *(const float4*)(Whh + (size_t)(g * 512 + j0 + j) * 512 + c4 * 4);
        *(float4*)&sW[row * SW_STRIDE + c4 * 4] = v;
    }
    if (tid < 128) sC[tid] = 0.f;
    __syncthreads();

    if (tid < 128) {
        int b = tid >> 2, jl = tid & 3;
        int j = j0 + jl;
        size_t gxb = (size_t)b * GD + j;
        float gi = g_gx[gxb +    0];
        float gg = g_gx[gxb + 1024];
        float go = g_gx[gxb + 1536];
        float si = 1.f / (1.f + expf(-gi));
        float tg = tanhf(gg);
        float so = 1.f / (1.f + expf(-go));
        float c = si * tg;
        sC[tid] = c;
        float h = so * tanhf(c);
        g_hbuf[0][b * 512 + j] = h;
        g_hs[(size_t)b * 512 + j] = h;
    }
    __threadfence();

    for (int t = 1; t < T1; t++) {
        grid_barrier(128u * (unsigned)t);

        const float* hsrc = g_hbuf[(t - 1) & 1];
        for (int i = tid; i < 4096; i += 256) {
            int b = i >> 7, c4 = i & 127;
            float4 v = __ldcg((const float4*)(hsrc + i * 4));
            *(float4*)&sH[b * SH_STRIDE + c4 * 4] = v;
        }
        __syncthreads();

        float acc[4][4];
#pragma unroll
        for (int ib = 0; ib < 4; ib++)
#pragma unroll
            for (int g = 0; g < 4; g++) acc[ib][g] = 0.f;

        const int kb = ks * 64;
#pragma unroll
        for (int k4 = 0; k4 < 16; k4++) {
            const int kk = kb + k4 * 4;
            float4 w0 = *(const float4*)&sW[(0 * 4 + jj) * SW_STRIDE + kk];
            float4 w1 = *(const float4*)&sW[(1 * 4 + jj) * SW_STRIDE + kk];
            float4 w2 = *(const float4*)&sW[(2 * 4 + jj) * SW_STRIDE + kk];
            float4 w3 = *(const float4*)&sW[(3 * 4 + jj) * SW_STRIDE + kk];
#pragma unroll
            for (int ib = 0; ib < 4; ib++) {
                float4 hv = *(const float4*)&sH[(bq + 8 * ib) * SH_STRIDE + kk];
                acc[ib][0] += hv.x * w0.x + hv.y * w0.y + hv.z * w0.z + hv.w * w0.w;
                acc[ib][1] += hv.x * w1.x + hv.y * w1.y + hv.z * w1.z + hv.w * w1.w;
                acc[ib][2] += hv.x * w2.x + hv.y * w2.y + hv.z * w2.z + hv.w * w2.w;
                acc[ib][3] += hv.x * w3.x + hv.y * w3.y + hv.z * w3.z + hv.w * w3.w;
            }
        }
#pragma unroll
        for (int ib = 0; ib < 4; ib++) {
            int b = bq + 8 * ib;
            *(float4*)&sRed[((ks * 32 + b) * 4 + jj) * 4] =
                make_float4(acc[ib][0], acc[ib][1], acc[ib][2], acc[ib][3]);
        }
        __syncthreads();

        if (tid < 128) {
            int b = tid >> 2, jl = tid & 3;
            float4 s = make_float4(0.f, 0.f, 0.f, 0.f);
#pragma unroll
            for (int k = 0; k < 8; k++) {
                float4 p = *(const float4*)&sRed[((k * 32 + b) * 4 + jl) * 4];
                s.x += p.x; s.y += p.y; s.z += p.z; s.w += p.w;
            }
            int j = j0 + jl;
            size_t gxb = ((size_t)t * 32 + b) * GD + j;
            float gi = s.x + g_gx[gxb +    0];
            float gf = s.y + g_gx[gxb +  512];
            float gg = s.z + g_gx[gxb + 1024];
            float go = s.w + g_gx[gxb + 1536];
            float si = 1.f / (1.f + expf(-gi));
            float sf = 1.f / (1.f + expf(-gf));
            float tg = tanhf(gg);
            float so = 1.f / (1.f + expf(-go));
            float c = sf * sC[tid] + si * tg;
            sC[tid] = c;
            float h = so * tanhf(c);
            g_hbuf[t & 1][b * 512 + j] = h;
            g_hs[((size_t)t * 32 + b) * 512 + j] = h;
        }
        __threadfence();
    }
}

// ---------------------------------------------------------------------------
// fp32 -> (bf16 hi, bf16 lo) split converters
// ---------------------------------------------------------------------------
__device__ __forceinline__ void split2(float x, __nv_bfloat16& h, __nv_bfloat16& l) {
    h = __float2bfloat16_rn(x);
    l = __float2bfloat16_rn(x - __bfloat162float(h));
}
__global__ void convert_w(const float* __restrict__ W) {
    size_t i = ((size_t)blockIdx.x * 256 + threadIdx.x) * 4;
    float4 v = *(const float4*)(W + i);
    __nv_bfloat16 h0, l0, h1, l1, h2, l2, h3, l3;
    split2(v.x, h0, l0); split2(v.y, h1, l1);
    split2(v.z, h2, l2); split2(v.w, h3, l3);
    uint2 oh, ol;
    oh.x = (uint32_t)__bfloat16_as_ushort(h0) | ((uint32_t)__bfloat16_as_ushort(h1) << 16);
    oh.y = (uint32_t)__bfloat16_as_ushort(h2) | ((uint32_t)__bfloat16_as_ushort(h3) << 16);
    ol.x = (uint32_t)__bfloat16_as_ushort(l0) | ((uint32_t)__bfloat16_as_ushort(l1) << 16);
    ol.y = (uint32_t)__bfloat16_as_ushort(l2) | ((uint32_t)__bfloat16_as_ushort(l3) << 16);
    *(uint2*)(g_wbh + i) = oh;
    *(uint2*)(g_wbl + i) = ol;
}
__global__ void convert_hs() {
    size_t i = ((size_t)blockIdx.x * 256 + threadIdx.x) * 4;
    float4 v = *(const float4*)(g_hs + i);
    __nv_bfloat16 h0, l0, h1, l1, h2, l2, h3, l3;
    split2(v.x, h0, l0); split2(v.y, h1, l1);
    split2(v.z, h2, l2); split2(v.w, h3, l3);
    uint2 oh, ol;
    oh.x = (uint32_t)__bfloat16_as_ushort(h0) | ((uint32_t)__bfloat16_as_ushort(h1) << 16);
    oh.y = (uint32_t)__bfloat16_as_ushort(h2) | ((uint32_t)__bfloat16_as_ushort(h3) << 16);
    ol.x = (uint32_t)__bfloat16_as_ushort(l0) | ((uint32_t)__bfloat16_as_ushort(l1) << 16);
    ol.y = (uint32_t)__bfloat16_as_ushort(l2) | ((uint32_t)__bfloat16_as_ushort(l3) << 16);
    *(uint2*)(g_hsh + i) = oh;
    *(uint2*)(g_hsl + i) = ol;
}

// ---------------------------------------------------------------------------
// Logits GEMM via bf16x3 mma.sync: D = hi.hi + hi.lo + lo.hi (fp32 accum).
// M=2016, N=32000, K=512. CTA tile 128x128, k-chunk 32, cp.async dbl-buffer.
// Dynamic smem: A[2buf][2split][128*SAP] bf16, B same, + bias.
// ---------------------------------------------------------------------------
#define SAP 40
#define TILEB (128 * SAP * 2)   // 10240 B
#define BUFB  (2 * TILEB)       // hi+lo per buffer
#define AB_REGION (2 * BUFB)    // 40960 B per tensor
#define TC_SMEM (2 * AB_REGION + 512)

#define ISSUE_CHUNK(ch) do { \
    int _buf = (ch) & 1; int _k0 = (ch) * 32; \
    _Pragma("unroll") \
    for (int _it = 0; _it < 8; _it++) { \
        const int _sel = _it >> 1; /* 0:Ahi 1:Alo 2:Bhi 3:Blo */ \
        int _rem = tid + (_it & 1) * 256; \
        int _r = _rem >> 2, _c8 = (_rem & 3) * 8; \
        uint32_t _dst = (_sel < 2 ? sAu : sBu) + _buf * BUFB \
                      + (_sel & 1) * TILEB + (uint32_t)(_r * SAP + _c8) * 2; \
        if (_sel < 2) { \
            int _gm = m0 + _r; \
            const __nv_bfloat16* _src = (_sel == 0 ? g_hsh : g_hsl) \
                + (size_t)(_gm < MR ? _gm : 0) * HH + _k0 + _c8; \
            int _sz = (_gm < MR) ? 16 : 0; \
            asm volatile("cp.async.cg.shared.global [%0], [%1], 16, %2;\n" \
                         :: "r"(_dst), "l"(_src), "r"(_sz)); \
        } else { \
            const __nv_bfloat16* _src = (_sel == 2 ? g_wbh : g_wbl) \
                + (size_t)(n0 + _r) * HH + _k0 + _c8; \
            asm volatile("cp.async.cg.shared.global [%0], [%1], 16;\n" \
                         :: "r"(_dst), "l"(_src)); \
        } \
    } \
    asm volatile("cp.async.commit_group;\n"); \
} while (0)

__global__ __launch_bounds__(256) void gemm_logits_bf16x3(
    const float* __restrict__ bias, float* __restrict__ out)
{
    extern __shared__ char dyn[];
    const uint32_t sAu = smem_u32(dyn);
    const uint32_t sBu = sAu + AB_REGION;
    float* sbias = (float*)(dyn + 2 * AB_REGION);

    const int tid = threadIdx.x, lane = tid & 31, wid = tid >> 5;
    const int m0 = blockIdx.x * 128, n0 = blockIdx.y * 128;
    const int wm = (wid & 1) * 64, wn = (wid >> 1) * 32;

    if (tid < 128) sbias[tid] = bias[n0 + tid];

    const int rowA = lane & 15;
    const int kA   = (lane >> 4) << 3;
    const int rowB = (lane & 7) + ((lane >> 4) << 3);
    const int kB   = (lane & 8) ? 8 : 0;

    float c[4][4][4];
#pragma unroll
    for (int mi = 0; mi < 4; mi++)
#pragma unroll
        for (int ni = 0; ni < 4; ni++)
#pragma unroll
            for (int q = 0; q < 4; q++) c[mi][ni][q] = 0.f;

    ISSUE_CHUNK(0);

    for (int ch = 0; ch < 16; ch++) {
        const int buf = ch & 1;
        if (ch < 15) {
            ISSUE_CHUNK(ch + 1);
            asm volatile("cp.async.wait_group 1;\n");
        } else {
            asm volatile("cp.async.wait_group 0;\n");
        }
        __syncthreads();

#pragma unroll
        for (int kk = 0; kk < 32; kk += 16) {
            uint32_t aH[4][4], aL[4][4], bH[4][2], bL[4][2];
#pragma unroll
            for (int mi = 0; mi < 4; mi++) {
                uint32_t base = sAu + buf * BUFB +
                    (uint32_t)((wm + mi * 16 + rowA) * SAP + kk + kA) * 2;
                LDMX4(aH[mi], base);
                LDMX4(aL[mi], base + TILEB);
            }
#pragma unroll
            for (int nb = 0; nb < 2; nb++) {
                uint32_t base = sBu + buf * BUFB +
                    (uint32_t)((wn + nb * 16 + rowB) * SAP + kk + kB) * 2;
                uint32_t r4[4];
                LDMX4(r4, base);
                bH[2 * nb][0] = r4[0]; bH[2 * nb][1] = r4[1];
                bH[2 * nb + 1][0] = r4[2]; bH[2 * nb + 1][1] = r4[3];
                LDMX4(r4, base + TILEB);
                bL[2 * nb][0] = r4[0]; bL[2 * nb][1] = r4[1];
                bL[2 * nb + 1][0] = r4[2]; bL[2 * nb + 1][1] = r4[3];
            }
#pragma unroll
            for (int mi = 0; mi < 4; mi++)
#pragma unroll
                for (int ni = 0; ni < 4; ni++) {
                    MMA16816(c[mi][ni], aH[mi], bH[ni][0], bH[ni][1]);
                    MMA16816(c[mi][ni], aH[mi], bL[ni][0], bL[ni][1]);
                    MMA16816(c[mi][ni], aL[mi], bH[ni][0], bH[ni][1]);
                }
        }
        __syncthreads();
    }

    const int erow = lane >> 2;
    const int ecol = (lane & 3) * 2;
#pragma unroll
    for (int mi = 0; mi < 4; mi++) {
#pragma unroll
        for (int half = 0; half < 2; half++) {
            int gm = m0 + wm + mi * 16 + erow + half * 8;
            if (gm < MR) {
                int tt = gm >> 5, b = gm & 31;
                float* dst = out + (size_t)(b * 63 + tt) * VV + n0 + wn;
#pragma unroll
                for (int ni = 0; ni < 4; ni++) {
                    float2 o;
                    o.x = c[mi][ni][half * 2 + 0] + sbias[wn + ni * 8 + ecol + 0];
                    o.y = c[mi][ni][half * 2 + 1] + sbias[wn + ni * 8 + ecol + 1];
                    *(float2*)(dst + ni * 8 + ecol) = o;
                }
            }
        }
    }
}

// ---------------------------------------------------------------------------
// Rescue: approx max -> candidates within DELTA -> exact fp32 recompute.
// ---------------------------------------------------------------------------
#define DELTA 0.005f
__global__ void rowmax_rescue(const float* __restrict__ logits,
                              const float* __restrict__ Wout,
                              const float* __restrict__ bout,
                              float* __restrict__ probs, float* __restrict__ pred)
{
    const int r = blockIdx.x;
    const int tid = threadIdx.x, lane = tid & 31, wid = tid >> 5;
    const float* row = logits + (size_t)r * VV;

    __shared__ float redv[256];
    float best = -INFINITY;
    for (int v = tid; v < VV; v += 256) best = fmaxf(best, row[v]);
    redv[tid] = best;
    __syncthreads();
    for (int s = 128; s > 0; s >>= 1) {
        if (tid < s) redv[tid] = fmaxf(redv[tid], redv[tid + s]);
        __syncthreads();
    }
    const float amax = redv[0];
    __syncthreads();

    __shared__ int cnt;
    __shared__ int cidx[128];
    __shared__ float cval[128];
    if (tid == 0) cnt = 0;
    __syncthreads();
    for (int v = tid; v < VV; v += 256) {
        if (row[v] > amax - DELTA) {
            int p = atomicAdd(&cnt, 1);
            if (p < 128) cidx[p] = v;
        }
    }
    __syncthreads();
    const int n = min(cnt, 128);

    const int b = r / 63, t = r % 63;
    const float* h = g_hs + ((size_t)t * 32 + b) * HH;

    for (int ci = wid; ci < n; ci += 8) {
        const float* w = Wout + (size_t)cidx[ci] * HH;
        float s = 0.f;
        const int kb = lane * 16;
#pragma unroll
        for (int j = 0; j < 4; j++) {
            float4 hv = *(const float4*)(h + kb + j * 4);
            float4 wv = __ldg((const float4*)(w + kb + j * 4));
            s += hv.x * wv.x + hv.y * wv.y + hv.z * wv.z + hv.w * wv.w;
        }
#pragma unroll
        for (int off = 16; off > 0; off >>= 1)
            s += __shfl_xor_sync(0xFFFFFFFF, s, off);
        if (lane == 0) cval[ci] = s + __ldg(bout + cidx[ci]);
    }
    __syncthreads();

    if (tid == 0) {
        float bv = -INFINITY; int bi = VV;
        for (int i = 0; i < n; i++) {
            float v = cval[i]; int ix = cidx[i];
            if (v > bv || (v == bv && ix < bi)) { bv = v; bi = ix; }
        }
        probs[r] = bv;
        pred[r] = (float)bi;
    }
}

// ---------------------------------------------------------------------------
extern "C" void kernel_launch(void* const* d_in, const int* in_sizes, int n_in,
                              void* d_out, int out_size)
{
    const float* enc  = (const float*)d_in[0];
    const int*   cap  = (const int*)  d_in[1];
    const float* emb  = (const float*)d_in[2];
    const float* Wih  = (const float*)d_in[3];
    const float* Whh  = (const float*)d_in[4];
    const float* bih  = (const float*)d_in[5];
    const float* bhh  = (const float*)d_in[6];
    const float* Wout = (const float*)d_in[7];
    const float* bout = (const float*)d_in[8];
    float* out = (float*)d_out;

    cudaFuncSetAttribute(lstm_persist,
                         cudaFuncAttributeMaxDynamicSharedMemorySize, SMEM_BYTES);
    cudaFuncSetAttribute(gemm_logits_bf16x3,
                         cudaFuncAttributeMaxDynamicSharedMemorySize, TC_SMEM);

    init_kernel<<<1, 32>>>();
    convert_w<<<16000, 256>>>(Wout);
    gemm_gx<<<dim3(16, 16), 256>>>(enc, cap, emb, Wih, bih, bhh);
    lstm_persist<<<128, 256, SMEM_BYTES>>>(Whh);
    convert_hs<<<1008, 256>>>();
    gemm_logits_bf16x3<<<dim3(16, 250), 256, TC_SMEM>>>(bout, out);

    const long logits_elems = (long)BB * T1 * VV;
    if ((long)out_size >= logits_elems + 2L * BB * T1) {
        rowmax_rescue<<<MR, 256>>>(out, Wout, bout,
                                   out + logits_elems,
                                   out + logits_elems + (long)BB * T1);
    }
}

// round 6
// speedup vs baseline: 2.3785x; 1.2380x over previous
#include <cuda_runtime.h>
#include <cuda_bf16.h>
#include <cuda_fp16.h>
#include <math.h>
#include <stdint.h>

// Problem dims
#define T1 63
#define BB 32
#define HH 512
#define VV 32000
#define MR (T1*BB)       // 2016
#define GD (4*HH)        // 2048

// Scratch (device globals)
__device__ float g_gx[(size_t)MR * GD];
__device__ float g_hs[(size_t)MR * HH];
__device__ float g_hbuf[2][BB * HH];
__device__ unsigned g_bar;
__device__ __half g_wh[(size_t)VV * HH];    // W_out fp16
__device__ __half g_hsh[(size_t)MR * HH];   // h states fp16

// ---------------- persistent-LSTM (64 CTAs x 512 thr) smem ----------------
#define SW_STRIDE 524                 // 32 W rows, padded
#define SH_STRIDE 516                 // 32 h rows, padded
#define SW_FLOATS (32 * SW_STRIDE)    // 16768
#define SH_FLOATS (32 * SH_STRIDE)    // 16512
#define SRED_FLOATS (8 * 32 * 8 * 4)  // 8192
#define SC_FLOATS 256
#define SMEM_FLOATS (SW_FLOATS + SH_FLOATS + SRED_FLOATS + SC_FLOATS)
#define SMEM_BYTES (SMEM_FLOATS * 4)  // 166,912 B
#define NCTA 64

__device__ __forceinline__ uint32_t smem_u32(const void* p) {
    uint32_t a;
    asm("{ .reg .u64 t; cvta.to.shared.u64 t, %1; cvt.u32.u64 %0, t; }"
        : "=r"(a) : "l"(p));
    return a;
}

#define LDMX4(R, addr) \
    asm volatile("ldmatrix.sync.aligned.m8n8.x4.shared.b16 {%0,%1,%2,%3}, [%4];" \
        : "=r"((R)[0]), "=r"((R)[1]), "=r"((R)[2]), "=r"((R)[3]) : "r"(addr))

#define MMA16816F(C, A, B0, B1) \
    asm volatile("mma.sync.aligned.m16n8k16.row.col.f32.f16.f16.f32 " \
        "{%0,%1,%2,%3}, {%4,%5,%6,%7}, {%8,%9}, {%0,%1,%2,%3};" \
        : "+f"((C)[0]), "+f"((C)[1]), "+f"((C)[2]), "+f"((C)[3]) \
        : "r"((A)[0]), "r"((A)[1]), "r"((A)[2]), "r"((A)[3]), "r"(B0), "r"(B1))

// ---------------------------------------------------------------------------
__global__ void init_kernel() {
    if (threadIdx.x == 0 && blockIdx.x == 0) g_bar = 0u;
}

// ---------------------------------------------------------------------------
// SGEMM 1 (fp32, unchanged): g_gx = xs @ W_ih^T + b_ih + b_hh
// ---------------------------------------------------------------------------
__global__ __launch_bounds__(256, 2) void gemm_gx(
    const float* __restrict__ enc, const int* __restrict__ cap,
    const float* __restrict__ emb, const float* __restrict__ W,
    const float* __restrict__ bih, const float* __restrict__ bhh)
{
    __shared__ float As[16][132];
    __shared__ float Bs[16][132];
    const int tid = threadIdx.x;
    const int m0 = blockIdx.y * 128, n0 = blockIdx.x * 128;
    const int lr = tid >> 2, lc = (tid & 3) << 2;
    const int tr = (tid >> 4) << 3, tc = (tid & 15) << 3;

    float acc[8][8];
#pragma unroll
    for (int i = 0; i < 8; i++)
#pragma unroll
        for (int j = 0; j < 8; j++) acc[i][j] = 0.f;

    for (int k0 = 0; k0 < 1024; k0 += 16) {
#pragma unroll
        for (int i = 0; i < 2; i++) {
            int row = m0 + lr + i * 64;
            float4 v = make_float4(0.f, 0.f, 0.f, 0.f);
            if (row < MR) {
                int tt = row >> 5, b = row & 31;
                int k = k0 + lc;
                const float* src = (k < 512)
                    ? (enc + b * 512 + k)
                    : (emb + (size_t)cap[b * 64 + tt] * 512 + (k - 512));
                v = *(const float4*)src;
            }
            As[lc + 0][lr + i * 64] = v.x;
            As[lc + 1][lr + i * 64] = v.y;
            As[lc + 2][lr + i * 64] = v.z;
            As[lc + 3][lr + i * 64] = v.w;
        }
#pragma unroll
        for (int i = 0; i < 2; i++) {
            int n = n0 + lr + i * 64;
            float4 v = *(const float4*)(W + (size_t)n * 1024 + k0 + lc);
            Bs[lc + 0][lr + i * 64] = v.x;
            Bs[lc + 1][lr + i * 64] = v.y;
            Bs[lc + 2][lr + i * 64] = v.z;
            Bs[lc + 3][lr + i * 64] = v.w;
        }
        __syncthreads();
#pragma unroll
        for (int kk = 0; kk < 16; kk++) {
            float a[8], bf[8];
            *(float4*)(a)     = *(float4*)&As[kk][tr];
            *(float4*)(a + 4) = *(float4*)&As[kk][tr + 4];
            *(float4*)(bf)     = *(float4*)&Bs[kk][tc];
            *(float4*)(bf + 4) = *(float4*)&Bs[kk][tc + 4];
#pragma unroll
            for (int i = 0; i < 8; i++)
#pragma unroll
                for (int j = 0; j < 8; j++) acc[i][j] += a[i] * bf[j];
        }
        __syncthreads();
    }
#pragma unroll
    for (int i = 0; i < 8; i++) {
        int row = m0 + tr + i;
        if (row < MR) {
#pragma unroll
            for (int j = 0; j < 8; j++) {
                int col = n0 + tc + j;
                g_gx[(size_t)row * GD + col] = acc[i][j] + bih[col] + bhh[col];
            }
        }
    }
}

// ---------------------------------------------------------------------------
// Persistent LSTM: 64 CTAs x 512 threads, CTA owns 8 j-columns.
// thread = (ks 0..7 K-chunk64) x (bq 0..7) x (jj 0..7); 4 batches/thread.
// ---------------------------------------------------------------------------
__device__ __forceinline__ void grid_barrier(unsigned target) {
    __syncthreads();
    if (threadIdx.x == 0) {
        unsigned a = atomicAdd(&g_bar, 1u) + 1u;
        if (a < target) {
            while (*(volatile unsigned*)&g_bar < target) { }
        }
    }
    __syncthreads();
}

__global__ __launch_bounds__(512, 1) void lstm_persist(const float* __restrict__ Whh)
{
    extern __shared__ float sm[];
    float* sW   = sm;                    // [32][524], row = g*8 + j
    float* sH   = sm + SW_FLOATS;        // [32][516]
    float* sRed = sH + SH_FLOATS;        // [ks8][b32][jj8][g4]
    float* sC   = sRed + SRED_FLOATS;    // [256] = b*8 + jl

    const int tid = threadIdx.x;
    const int j0 = blockIdx.x * 8;
    const int jj = tid & 7;
    const int bq = (tid >> 3) & 7;
    const int ks = tid >> 6;             // 0..7

    // Stage 32 W_hh rows (g*512 + j0 + j) once.
    for (int i = tid; i < 32 * 128; i += 512) {   // float4 units
        int row = i >> 7, c4 = i & 127;
        int g = row >> 3, j = row & 7;
        float4 v = *(const float4*)(Whh + (size_t)(g * 512 + j0 + j) * 512 + c4 * 4);
        *(float4*)&sW[row * SW_STRIDE + c4 * 4] = v;
    }
    if (tid < 256) sC[tid] = 0.f;
    __syncthreads();

    // step 0: h=0
    if (tid < 256) {
        int b = tid >> 3, jl = tid & 7;
        int j = j0 + jl;
        size_t gxb = (size_t)b * GD + j;
        float gi = g_gx[gxb +    0];
        float gg = g_gx[gxb + 1024];
        float go = g_gx[gxb + 1536];
        float si = 1.f / (1.f + expf(-gi));
        float tg = tanhf(gg);
        float so = 1.f / (1.f + expf(-go));
        float c = si * tg;
        sC[tid] = c;
        float h = so * tanhf(c);
        g_hbuf[0][b * 512 + j] = h;
        g_hs[(size_t)b * 512 + j] = h;
    }
    __threadfence();

    for (int t = 1; t < T1; t++) {
        grid_barrier((unsigned)NCTA * (unsigned)t);

        const float* hsrc = g_hbuf[(t - 1) & 1];
        for (int i = tid; i < 4096; i += 512) {   // float4 units
            int b = i >> 7, c4 = i & 127;
            float4 v = __ldcg((const float4*)(hsrc + i * 4));
            *(float4*)&sH[b * SH_STRIDE + c4 * 4] = v;
        }
        __syncthreads();

        float acc[4][4];
#pragma unroll
        for (int ib = 0; ib < 4; ib++)
#pragma unroll
            for (int g = 0; g < 4; g++) acc[ib][g] = 0.f;

        const int kb = ks * 64;
#pragma unroll
        for (int k4 = 0; k4 < 16; k4++) {
            const int kk = kb + k4 * 4;
            float4 w0 = *(const float4*)&sW[(0 * 8 + jj) * SW_STRIDE + kk];
            float4 w1 = *(const float4*)&sW[(1 * 8 + jj) * SW_STRIDE + kk];
            float4 w2 = *(const float4*)&sW[(2 * 8 + jj) * SW_STRIDE + kk];
            float4 w3 = *(const float4*)&sW[(3 * 8 + jj) * SW_STRIDE + kk];
#pragma unroll
            for (int ib = 0; ib < 4; ib++) {
                float4 hv = *(const float4*)&sH[(bq + 8 * ib) * SH_STRIDE + kk];
                acc[ib][0] += hv.x * w0.x + hv.y * w0.y + hv.z * w0.z + hv.w * w0.w;
                acc[ib][1] += hv.x * w1.x + hv.y * w1.y + hv.z * w1.z + hv.w * w1.w;
                acc[ib][2] += hv.x * w2.x + hv.y * w2.y + hv.z * w2.z + hv.w * w2.w;
                acc[ib][3] += hv.x * w3.x + hv.y * w3.y + hv.z * w3.z + hv.w * w3.w;
            }
        }
#pragma unroll
        for (int ib = 0; ib < 4; ib++) {
            int b = bq + 8 * ib;
            *(float4*)&sRed[((ks * 32 + b) * 8 + jj) * 4] =
                make_float4(acc[ib][0], acc[ib][1], acc[ib][2], acc[ib][3]);
        }
        __syncthreads();

        if (tid < 256) {
            int b = tid >> 3, jl = tid & 7;
            float4 s = make_float4(0.f, 0.f, 0.f, 0.f);
#pragma unroll
            for (int k = 0; k < 8; k++) {
                float4 p = *(const float4*)&sRed[((k * 32 + b) * 8 + jl) * 4];
                s.x += p.x; s.y += p.y; s.z += p.z; s.w += p.w;
            }
            int j = j0 + jl;
            size_t gxb = ((size_t)t * 32 + b) * GD + j;
            float gi = s.x + g_gx[gxb +    0];
            float gf = s.y + g_gx[gxb +  512];
            float gg = s.z + g_gx[gxb + 1024];
            float go = s.w + g_gx[gxb + 1536];
            float si = 1.f / (1.f + expf(-gi));
            float sf = 1.f / (1.f + expf(-gf));
            float tg = tanhf(gg);
            float so = 1.f / (1.f + expf(-go));
            float c = sf * sC[tid] + si * tg;
            sC[tid] = c;
            float h = so * tanhf(c);
            g_hbuf[t & 1][b * 512 + j] = h;
            g_hs[((size_t)t * 32 + b) * 512 + j] = h;
        }
        __threadfence();
    }
}

// ---------------------------------------------------------------------------
// fp32 -> fp16 converters
// ---------------------------------------------------------------------------
__global__ void convert_w(const float* __restrict__ W) {
    size_t i = ((size_t)blockIdx.x * 256 + threadIdx.x) * 4;
    float4 v = *(const float4*)(W + i);
    __half2 a = __floats2half2_rn(v.x, v.y);
    __half2 b = __floats2half2_rn(v.z, v.w);
    uint2 o;
    o.x = *(uint32_t*)&a; o.y = *(uint32_t*)&b;
    *(uint2*)(g_wh + i) = o;
}
__global__ void convert_hs() {
    size_t i = ((size_t)blockIdx.x * 256 + threadIdx.x) * 4;
    float4 v = *(const float4*)(g_hs + i);
    __half2 a = __floats2half2_rn(v.x, v.y);
    __half2 b = __floats2half2_rn(v.z, v.w);
    uint2 o;
    o.x = *(uint32_t*)&a; o.y = *(uint32_t*)&b;
    *(uint2*)(g_hsh + i) = o;
}

// ---------------------------------------------------------------------------
// Logits GEMM via single-pass fp16 mma.sync (m16n8k16). M=2016,N=32000,K=512.
// CTA tile 128x128, k-chunk 32, cp.async double buffer, 8 warps (2m x 4n).
// ---------------------------------------------------------------------------
#define SAP 40

#define ISSUE_CHUNK(ch) do { \
    int _buf = (ch) & 1; int _k0 = (ch) * 32; \
    _Pragma("unroll") \
    for (int _it = 0; _it < 2; _it++) { \
        int _idx = tid + _it * 256; \
        int _r = _idx >> 2, _c8 = (_idx & 3) * 8; \
        int _gm = m0 + _r; \
        const __half* _srcA = g_hsh + (size_t)(_gm < MR ? _gm : 0) * HH + _k0 + _c8; \
        uint32_t _dstA = sAu + _buf * BUFB + (_r * SAP + _c8) * 2; \
        int _szA = (_gm < MR) ? 16 : 0; \
        asm volatile("cp.async.cg.shared.global [%0], [%1], 16, %2;\n" \
                     :: "r"(_dstA), "l"(_srcA), "r"(_szA)); \
        const __half* _srcB = g_wh + (size_t)(n0 + _r) * HH + _k0 + _c8; \
        uint32_t _dstB = sBu + _buf * BUFB + (_r * SAP + _c8) * 2; \
        asm volatile("cp.async.cg.shared.global [%0], [%1], 16;\n" \
                     :: "r"(_dstB), "l"(_srcB)); \
    } \
    asm volatile("cp.async.commit_group;\n"); \
} while (0)

__global__ __launch_bounds__(256) void gemm_logits_f16(
    const float* __restrict__ bias, float* __restrict__ out)
{
    __shared__ __half sA[2][128 * SAP];
    __shared__ __half sB[2][128 * SAP];
    __shared__ float sbias[128];

    const int tid = threadIdx.x, lane = tid & 31, wid = tid >> 5;
    const int m0 = blockIdx.x * 128, n0 = blockIdx.y * 128;
    const int wm = (wid & 1) * 64, wn = (wid >> 1) * 32;
    const uint32_t BUFB = 128 * SAP * 2;

    if (tid < 128) sbias[tid] = bias[n0 + tid];

    const uint32_t sAu = smem_u32(sA);
    const uint32_t sBu = smem_u32(sB);

    const int rowA = lane & 15;
    const int kA   = (lane >> 4) << 3;
    const int rowB = (lane & 7) + ((lane >> 4) << 3);
    const int kB   = (lane & 8) ? 8 : 0;

    float c[4][4][4];
#pragma unroll
    for (int mi = 0; mi < 4; mi++)
#pragma unroll
        for (int ni = 0; ni < 4; ni++)
#pragma unroll
            for (int q = 0; q < 4; q++) c[mi][ni][q] = 0.f;

    ISSUE_CHUNK(0);

    for (int ch = 0; ch < 16; ch++) {
        const int buf = ch & 1;
        if (ch < 15) {
            ISSUE_CHUNK(ch + 1);
            asm volatile("cp.async.wait_group 1;\n");
        } else {
            asm volatile("cp.async.wait_group 0;\n");
        }
        __syncthreads();

#pragma unroll
        for (int kk = 0; kk < 32; kk += 16) {
            uint32_t aF[4][4], bF[4][2];
#pragma unroll
            for (int mi = 0; mi < 4; mi++) {
                uint32_t ad = sAu + buf * BUFB +
                    (uint32_t)((wm + mi * 16 + rowA) * SAP + kk + kA) * 2;
                LDMX4(aF[mi], ad);
            }
#pragma unroll
            for (int nb = 0; nb < 2; nb++) {
                uint32_t r4[4];
                uint32_t bd = sBu + buf * BUFB +
                    (uint32_t)((wn + nb * 16 + rowB) * SAP + kk + kB) * 2;
                LDMX4(r4, bd);
                bF[2 * nb][0] = r4[0]; bF[2 * nb][1] = r4[1];
                bF[2 * nb + 1][0] = r4[2]; bF[2 * nb + 1][1] = r4[3];
            }
#pragma unroll
            for (int mi = 0; mi < 4; mi++)
#pragma unroll
                for (int ni = 0; ni < 4; ni++)
                    MMA16816F(c[mi][ni], aF[mi], bF[ni][0], bF[ni][1]);
        }
        __syncthreads();
    }

    const int erow = lane >> 2;
    const int ecol = (lane & 3) * 2;
#pragma unroll
    for (int mi = 0; mi < 4; mi++) {
#pragma unroll
        for (int half = 0; half < 2; half++) {
            int gm = m0 + wm + mi * 16 + erow + half * 8;
            if (gm < MR) {
                int tt = gm >> 5, b = gm & 31;
                float* dst = out + (size_t)(b * 63 + tt) * VV + n0 + wn;
#pragma unroll
                for (int ni = 0; ni < 4; ni++) {
                    float2 o;
                    o.x = c[mi][ni][half * 2 + 0] + sbias[wn + ni * 8 + ecol + 0];
                    o.y = c[mi][ni][half * 2 + 1] + sbias[wn + ni * 8 + ecol + 1];
                    *(float2*)(dst + ni * 8 + ecol) = o;
                }
            }
        }
    }
}

// ---------------------------------------------------------------------------
// Rescue: approx max -> candidates within DELTA -> exact fp32 recompute.
// ---------------------------------------------------------------------------
#define DELTA 0.01f
__global__ void rowmax_rescue(const float* __restrict__ logits,
                              const float* __restrict__ Wout,
                              const float* __restrict__ bout,
                              float* __restrict__ probs, float* __restrict__ pred)
{
    const int r = blockIdx.x;
    const int tid = threadIdx.x, lane = tid & 31, wid = tid >> 5;
    const float* row = logits + (size_t)r * VV;

    __shared__ float redv[256];
    float best = -INFINITY;
    for (int v = tid; v < VV; v += 256) best = fmaxf(best, row[v]);
    redv[tid] = best;
    __syncthreads();
    for (int s = 128; s > 0; s >>= 1) {
        if (tid < s) redv[tid] = fmaxf(redv[tid], redv[tid + s]);
        __syncthreads();
    }
    const float amax = redv[0];
    __syncthreads();

    __shared__ int cnt;
    __shared__ int cidx[128];
    __shared__ float cval[128];
    if (tid == 0) cnt = 0;
    __syncthreads();
    for (int v = tid; v < VV; v += 256) {
        if (row[v] > amax - DELTA) {
            int p = atomicAdd(&cnt, 1);
            if (p < 128) cidx[p] = v;
        }
    }
    __syncthreads();
    const int n = min(cnt, 128);

    const int b = r / 63, t = r % 63;
    const float* h = g_hs + ((size_t)t * 32 + b) * HH;

    for (int ci = wid; ci < n; ci += 8) {
        const float* w = Wout + (size_t)cidx[ci] * HH;
        float s = 0.f;
        const int kb = lane * 16;
#pragma unroll
        for (int j = 0; j < 4; j++) {
            float4 hv = *(const float4*)(h + kb + j * 4);
            float4 wv = __ldg((const float4*)(w + kb + j * 4));
            s += hv.x * wv.x + hv.y * wv.y + hv.z * wv.z + hv.w * wv.w;
        }
#pragma unroll
        for (int off = 16; off > 0; off >>= 1)
            s += __shfl_xor_sync(0xFFFFFFFF, s, off);
        if (lane == 0) cval[ci] = s + __ldg(bout + cidx[ci]);
    }
    __syncthreads();

    if (tid == 0) {
        float bv = -INFINITY; int bi = VV;
        for (int i = 0; i < n; i++) {
            float v = cval[i]; int ix = cidx[i];
            if (v > bv || (v == bv && ix < bi)) { bv = v; bi = ix; }
        }
        probs[r] = bv;
        pred[r] = (float)bi;
    }
}

// ---------------------------------------------------------------------------
extern "C" void kernel_launch(void* const* d_in, const int* in_sizes, int n_in,
                              void* d_out, int out_size)
{
    const float* enc  = (const float*)d_in[0];
    const int*   cap  = (const int*)  d_in[1];
    const float* emb  = (const float*)d_in[2];
    const float* Wih  = (const float*)d_in[3];
    const float* Whh  = (const float*)d_in[4];
    const float* bih  = (const float*)d_in[5];
    const float* bhh  = (const float*)d_in[6];
    const float* Wout = (const float*)d_in[7];
    const float* bout = (const float*)d_in[8];
    float* out = (float*)d_out;

    cudaFuncSetAttribute(lstm_persist,
                         cudaFuncAttributeMaxDynamicSharedMemorySize, SMEM_BYTES);

    init_kernel<<<1, 32>>>();
    convert_w<<<16000, 256>>>(Wout);
    gemm_gx<<<dim3(16, 16), 256>>>(enc, cap, emb, Wih, bih, bhh);
    lstm_persist<<<NCTA, 512, SMEM_BYTES>>>(Whh);
    convert_hs<<<1008, 256>>>();
    gemm_logits_f16<<<dim3(16, 250), 256>>>(bout, out);

    const long logits_elems = (long)BB * T1 * VV;
    if ((long)out_size >= logits_elems + 2L * BB * T1) {
        rowmax_rescue<<<MR, 256>>>(out, Wout, bout,
                                   out + logits_elems,
                                   out + logits_elems + (long)BB * T1);
    }
}

// round 7
// speedup vs baseline: 3.2767x; 1.3776x over previous
#include <cuda_runtime.h>
#include <cuda_bf16.h>
#include <cuda_fp16.h>
#include <math.h>
#include <stdint.h>

// Problem dims
#define T1 63
#define BB 32
#define HH 512
#define VV 32000
#define MR (T1*BB)       // 2016
#define GD (4*HH)        // 2048
#define KX 1024          // xs K-dim
#define NTB 250          // logits n-blocks

// Scratch (device globals)
__device__ float g_gx[(size_t)MR * GD];
__device__ float g_hs[(size_t)MR * HH];
__device__ float g_hbuf[2][BB * HH];
__device__ unsigned g_bar;
__device__ __half g_wh[(size_t)VV * HH];      // W_out fp16
__device__ __half g_hsh[(size_t)MR * HH];     // h states fp16
__device__ __half g_wih_h[(size_t)GD * KX];   // W_ih hi
__device__ __half g_wih_l[(size_t)GD * KX];   // W_ih lo
__device__ __half g_xs_h[(size_t)MR * KX];    // xs hi
__device__ __half g_xs_l[(size_t)MR * KX];    // xs lo
__device__ unsigned g_tmax[(size_t)MR * NTB]; // per-(row, nblock) max key

// ---------------- persistent-LSTM (128 CTAs x 512 thr) smem ----------------
#define SW_STRIDE 520
#define SH_STRIDE 516
#define SW_FLOATS (16 * SW_STRIDE)     // 8320
#define SH_FLOATS (32 * SH_STRIDE)     // 16512
#define SRED_FLOATS (16 * 32 * 4 * 4)  // 8192
#define SC_FLOATS 128
#define SMEM_FLOATS (SW_FLOATS + SH_FLOATS + SRED_FLOATS + SC_FLOATS)
#define SMEM_BYTES (SMEM_FLOATS * 4)   // 132,608 B
#define NCTA 128

__device__ __forceinline__ uint32_t smem_u32(const void* p) {
    uint32_t a;
    asm("{ .reg .u64 t; cvta.to.shared.u64 t, %1; cvt.u32.u64 %0, t; }"
        : "=r"(a) : "l"(p));
    return a;
}
__device__ __forceinline__ unsigned fkey(float x) {
    unsigned u = __float_as_uint(x);
    return (u & 0x80000000u) ? ~u : (u | 0x80000000u);
}
__device__ __forceinline__ float keyf(unsigned k) {
    unsigned u = (k & 0x80000000u) ? (k & 0x7FFFFFFFu) : ~k;
    return __uint_as_float(u);
}

#define LDMX4(R, addr) \
    asm volatile("ldmatrix.sync.aligned.m8n8.x4.shared.b16 {%0,%1,%2,%3}, [%4];" \
        : "=r"((R)[0]), "=r"((R)[1]), "=r"((R)[2]), "=r"((R)[3]) : "r"(addr))

#define MMA16816F(C, A, B0, B1) \
    asm volatile("mma.sync.aligned.m16n8k16.row.col.f32.f16.f16.f32 " \
        "{%0,%1,%2,%3}, {%4,%5,%6,%7}, {%8,%9}, {%0,%1,%2,%3};" \
        : "+f"((C)[0]), "+f"((C)[1]), "+f"((C)[2]), "+f"((C)[3]) \
        : "r"((A)[0]), "r"((A)[1]), "r"((A)[2]), "r"((A)[3]), "r"(B0), "r"(B1))

// ---------------------------------------------------------------------------
__global__ void init_kernel() {
    if (threadIdx.x == 0 && blockIdx.x == 0) g_bar = 0u;
}

// ---------------------------------------------------------------------------
// Converters
// ---------------------------------------------------------------------------
__device__ __forceinline__ void split16(float x, __half& h, __half& l) {
    h = __float2half_rn(x);
    l = __float2half_rn(x - __half2float(h));
}
__global__ void convert_w(const float* __restrict__ W) {
    size_t i = ((size_t)blockIdx.x * 256 + threadIdx.x) * 4;
    float4 v = *(const float4*)(W + i);
    __half2 a = __floats2half2_rn(v.x, v.y);
    __half2 b = __floats2half2_rn(v.z, v.w);
    uint2 o; o.x = *(uint32_t*)&a; o.y = *(uint32_t*)&b;
    *(uint2*)(g_wh + i) = o;
}
__global__ void convert_hs() {
    size_t i = ((size_t)blockIdx.x * 256 + threadIdx.x) * 4;
    float4 v = *(const float4*)(g_hs + i);
    __half2 a = __floats2half2_rn(v.x, v.y);
    __half2 b = __floats2half2_rn(v.z, v.w);
    uint2 o; o.x = *(uint32_t*)&a; o.y = *(uint32_t*)&b;
    *(uint2*)(g_hsh + i) = o;
}
__global__ void convert_wih(const float* __restrict__ W) {
    size_t i = ((size_t)blockIdx.x * 256 + threadIdx.x) * 4;
    float4 v = *(const float4*)(W + i);
    __half h0, l0, h1, l1, h2, l2, h3, l3;
    split16(v.x, h0, l0); split16(v.y, h1, l1);
    split16(v.z, h2, l2); split16(v.w, h3, l3);
    __half2 ha = __halves2half2(h0, h1), hb = __halves2half2(h2, h3);
    __half2 la = __halves2half2(l0, l1), lb = __halves2half2(l2, l3);
    uint2 oh, ol;
    oh.x = *(uint32_t*)&ha; oh.y = *(uint32_t*)&hb;
    ol.x = *(uint32_t*)&la; ol.y = *(uint32_t*)&lb;
    *(uint2*)(g_wih_h + i) = oh;
    *(uint2*)(g_wih_l + i) = ol;
}
// Build xs (gathered) as fp16 hi/lo. Row m = t*32+b: k<512 enc, else emb.
__global__ void build_xs(const float* __restrict__ enc, const int* __restrict__ cap,
                         const float* __restrict__ emb) {
    int i4 = blockIdx.x * 256 + threadIdx.x;   // float4 index
    int m = i4 >> 8;                            // 256 float4 per row
    int c4 = i4 & 255;
    int k = c4 * 4;
    int tt = m >> 5, b = m & 31;
    const float* src = (k < 512)
        ? (enc + b * 512 + k)
        : (emb + (size_t)__ldg(cap + b * 64 + tt) * 512 + (k - 512));
    float4 v = *(const float4*)src;
    __half h0, l0, h1, l1, h2, l2, h3, l3;
    split16(v.x, h0, l0); split16(v.y, h1, l1);
    split16(v.z, h2, l2); split16(v.w, h3, l3);
    __half2 ha = __halves2half2(h0, h1), hb = __halves2half2(h2, h3);
    __half2 la = __halves2half2(l0, l1), lb = __halves2half2(l2, l3);
    uint2 oh, ol;
    oh.x = *(uint32_t*)&ha; oh.y = *(uint32_t*)&hb;
    ol.x = *(uint32_t*)&la; ol.y = *(uint32_t*)&lb;
    size_t off = (size_t)m * KX + k;
    *(uint2*)(g_xs_h + off) = oh;
    *(uint2*)(g_xs_l + off) = ol;
}

// ---------------------------------------------------------------------------
// gx GEMM via fp16x2-split mma.sync: gx = hi.hi + hi.lo + lo.hi + biases.
// M=2016, N=2048, K=1024. CTA 128x128, k-chunk 32, cp.async dbl-buffer.
// ---------------------------------------------------------------------------
#define SAP 40
#define TILEB (128 * SAP * 2)   // 10240 B
#define BUFB  (2 * TILEB)
#define AB_REGION (2 * BUFB)
#define GX_SMEM (2 * AB_REGION + 512)

#define GX_ISSUE(ch) do { \
    int _buf = (ch) & 1; int _k0 = (ch) * 32; \
    _Pragma("unroll") \
    for (int _it = 0; _it < 8; _it++) { \
        const int _sel = _it >> 1; \
        int _rem = tid + (_it & 1) * 256; \
        int _r = _rem >> 2, _c8 = (_rem & 3) * 8; \
        uint32_t _dst = (_sel < 2 ? sAu : sBu) + _buf * BUFB \
                      + (_sel & 1) * TILEB + (uint32_t)(_r * SAP + _c8) * 2; \
        if (_sel < 2) { \
            int _gm = m0 + _r; \
            const __half* _src = (_sel == 0 ? g_xs_h : g_xs_l) \
                + (size_t)(_gm < MR ? _gm : 0) * KX + _k0 + _c8; \
            int _sz = (_gm < MR) ? 16 : 0; \
            asm volatile("cp.async.cg.shared.global [%0], [%1], 16, %2;\n" \
                         :: "r"(_dst), "l"(_src), "r"(_sz)); \
        } else { \
            const __half* _src = (_sel == 2 ? g_wih_h : g_wih_l) \
                + (size_t)(n0 + _r) * KX + _k0 + _c8; \
            asm volatile("cp.async.cg.shared.global [%0], [%1], 16;\n" \
                         :: "r"(_dst), "l"(_src)); \
        } \
    } \
    asm volatile("cp.async.commit_group;\n"); \
} while (0)

__global__ __launch_bounds__(256) void gemm_gx_f16(
    const float* __restrict__ bih, const float* __restrict__ bhh)
{
    extern __shared__ char dyn[];
    const uint32_t sAu = smem_u32(dyn);
    const uint32_t sBu = sAu + AB_REGION;
    float* sbias = (float*)(dyn + 2 * AB_REGION);

    const int tid = threadIdx.x, lane = tid & 31, wid = tid >> 5;
    const int m0 = blockIdx.x * 128, n0 = blockIdx.y * 128;
    const int wm = (wid & 1) * 64, wn = (wid >> 1) * 32;

    if (tid < 128) sbias[tid] = bih[n0 + tid] + bhh[n0 + tid];

    const int rowA = lane & 15;
    const int kA   = (lane >> 4) << 3;
    const int rowB = (lane & 7) + ((lane >> 4) << 3);
    const int kB   = (lane & 8) ? 8 : 0;

    float c[4][4][4];
#pragma unroll
    for (int mi = 0; mi < 4; mi++)
#pragma unroll
        for (int ni = 0; ni < 4; ni++)
#pragma unroll
            for (int q = 0; q < 4; q++) c[mi][ni][q] = 0.f;

    GX_ISSUE(0);

    for (int ch = 0; ch < 32; ch++) {
        const int buf = ch & 1;
        if (ch < 31) {
            GX_ISSUE(ch + 1);
            asm volatile("cp.async.wait_group 1;\n");
        } else {
            asm volatile("cp.async.wait_group 0;\n");
        }
        __syncthreads();

#pragma unroll
        for (int kk = 0; kk < 32; kk += 16) {
            uint32_t aH[4][4], aL[4][4], bH[4][2], bL[4][2];
#pragma unroll
            for (int mi = 0; mi < 4; mi++) {
                uint32_t base = sAu + buf * BUFB +
                    (uint32_t)((wm + mi * 16 + rowA) * SAP + kk + kA) * 2;
                LDMX4(aH[mi], base);
                LDMX4(aL[mi], base + TILEB);
            }
#pragma unroll
            for (int nb = 0; nb < 2; nb++) {
                uint32_t base = sBu + buf * BUFB +
                    (uint32_t)((wn + nb * 16 + rowB) * SAP + kk + kB) * 2;
                uint32_t r4[4];
                LDMX4(r4, base);
                bH[2 * nb][0] = r4[0]; bH[2 * nb][1] = r4[1];
                bH[2 * nb + 1][0] = r4[2]; bH[2 * nb + 1][1] = r4[3];
                LDMX4(r4, base + TILEB);
                bL[2 * nb][0] = r4[0]; bL[2 * nb][1] = r4[1];
                bL[2 * nb + 1][0] = r4[2]; bL[2 * nb + 1][1] = r4[3];
            }
#pragma unroll
            for (int mi = 0; mi < 4; mi++)
#pragma unroll
                for (int ni = 0; ni < 4; ni++) {
                    MMA16816F(c[mi][ni], aH[mi], bH[ni][0], bH[ni][1]);
                    MMA16816F(c[mi][ni], aH[mi], bL[ni][0], bL[ni][1]);
                    MMA16816F(c[mi][ni], aL[mi], bH[ni][0], bH[ni][1]);
                }
        }
        __syncthreads();
    }

    const int erow = lane >> 2;
    const int ecol = (lane & 3) * 2;
#pragma unroll
    for (int mi = 0; mi < 4; mi++) {
#pragma unroll
        for (int half = 0; half < 2; half++) {
            int gm = m0 + wm + mi * 16 + erow + half * 8;
            if (gm < MR) {
                float* dst = g_gx + (size_t)gm * GD + n0 + wn;
#pragma unroll
                for (int ni = 0; ni < 4; ni++) {
                    float2 o;
                    o.x = c[mi][ni][half * 2 + 0] + sbias[wn + ni * 8 + ecol + 0];
                    o.y = c[mi][ni][half * 2 + 1] + sbias[wn + ni * 8 + ecol + 1];
                    *(float2*)(dst + ni * 8 + ecol) = o;
                }
            }
        }
    }
}

// ---------------------------------------------------------------------------
// Persistent LSTM: 128 CTAs x 512 threads; 16-way K split; gx prefetch.
// ---------------------------------------------------------------------------
__device__ __forceinline__ void grid_barrier(unsigned target) {
    __syncthreads();
    if (threadIdx.x == 0) {
        unsigned a = atomicAdd(&g_bar, 1u) + 1u;
        if (a < target) {
            while (*(volatile unsigned*)&g_bar < target) { }
        }
    }
    __syncthreads();
}

__global__ __launch_bounds__(512, 1) void lstm_persist(const float* __restrict__ Whh)
{
    extern __shared__ float sm[];
    float* sW   = sm;                    // [16][520], row = g*4 + j
    float* sH   = sm + SW_FLOATS;        // [32][516]
    float* sRed = sH + SH_FLOATS;        // [ks16][b32][jj4][g4]
    float* sC   = sRed + SRED_FLOATS;    // [128]

    const int tid = threadIdx.x;
    const int j0 = blockIdx.x * 4;
    const int jj = tid & 3;
    const int bq = (tid >> 2) & 7;
    const int ks = tid >> 5;             // 0..15

    for (int i = tid; i < 16 * 128; i += 512) {   // float4 units
        int row = i >> 7, c4 = i & 127;
        int g = row >> 2, j = row & 3;
        float4 v = *(const float4*)(Whh + (size_t)(g * 512 + j0 + j) * 512 + c4 * 4);
        *(float4*)&sW[row * SW_STRIDE + c4 * 4] = v;
    }
    if (tid < 128) sC[tid] = 0.f;
    __syncthreads();

    const int bb = tid >> 2, jl = tid & 3;        // for tid<128 roles
    const int jcol = j0 + jl;

    // step 0: h=0
    if (tid < 128) {
        size_t gxb = (size_t)bb * GD + jcol;
        float gi = g_gx[gxb +    0];
        float gg = g_gx[gxb + 1024];
        float go = g_gx[gxb + 1536];
        float si = 1.f / (1.f + expf(-gi));
        float tg = tanhf(gg);
        float so = 1.f / (1.f + expf(-go));
        float c = si * tg;
        sC[tid] = c;
        float h = so * tanhf(c);
        g_hbuf[0][bb * 512 + jcol] = h;
        g_hs[(size_t)bb * 512 + jcol] = h;
    }
    __threadfence();

    // prefetch gx for t=1
    float4 pgx = make_float4(0.f, 0.f, 0.f, 0.f);
    if (tid < 128) {
        size_t gxb = ((size_t)1 * 32 + bb) * GD + jcol;
        pgx.x = __ldg(&g_gx[gxb +    0]);
        pgx.y = __ldg(&g_gx[gxb +  512]);
        pgx.z = __ldg(&g_gx[gxb + 1024]);
        pgx.w = __ldg(&g_gx[gxb + 1536]);
    }

    for (int t = 1; t < T1; t++) {
        grid_barrier((unsigned)NCTA * (unsigned)t);

        const float* hsrc = g_hbuf[(t - 1) & 1];
        for (int i = tid; i < 4096; i += 512) {   // float4 units
            int b = i >> 7, c4 = i & 127;
            float4 v = __ldcg((const float4*)(hsrc + i * 4));
            *(float4*)&sH[b * SH_STRIDE + c4 * 4] = v;
        }
        __syncthreads();

        float acc[4][4];
#pragma unroll
        for (int ib = 0; ib < 4; ib++)
#pragma unroll
            for (int g = 0; g < 4; g++) acc[ib][g] = 0.f;

        const int kb = ks * 32;
#pragma unroll
        for (int k4 = 0; k4 < 8; k4++) {
            const int kk = kb + k4 * 4;
            float4 w0 = *(const float4*)&sW[(0 * 4 + jj) * SW_STRIDE + kk];
            float4 w1 = *(const float4*)&sW[(1 * 4 + jj) * SW_STRIDE + kk];
            float4 w2 = *(const float4*)&sW[(2 * 4 + jj) * SW_STRIDE + kk];
            float4 w3 = *(const float4*)&sW[(3 * 4 + jj) * SW_STRIDE + kk];
#pragma unroll
            for (int ib = 0; ib < 4; ib++) {
                float4 hv = *(const float4*)&sH[(bq + 8 * ib) * SH_STRIDE + kk];
                acc[ib][0] += hv.x * w0.x + hv.y * w0.y + hv.z * w0.z + hv.w * w0.w;
                acc[ib][1] += hv.x * w1.x + hv.y * w1.y + hv.z * w1.z + hv.w * w1.w;
                acc[ib][2] += hv.x * w2.x + hv.y * w2.y + hv.z * w2.z + hv.w * w2.w;
                acc[ib][3] += hv.x * w3.x + hv.y * w3.y + hv.z * w3.z + hv.w * w3.w;
            }
        }
#pragma unroll
        for (int ib = 0; ib < 4; ib++) {
            int b = bq + 8 * ib;
            *(float4*)&sRed[((ks * 32 + b) * 4 + jj) * 4] =
                make_float4(acc[ib][0], acc[ib][1], acc[ib][2], acc[ib][3]);
        }
        __syncthreads();

        if (tid < 128) {
            float4 s = make_float4(0.f, 0.f, 0.f, 0.f);
#pragma unroll
            for (int k = 0; k < 16; k++) {
                float4 p = *(const float4*)&sRed[((k * 32 + bb) * 4 + jl) * 4];
                s.x += p.x; s.y += p.y; s.z += p.z; s.w += p.w;
            }
            float gi = s.x + pgx.x;
            float gf = s.y + pgx.y;
            float gg = s.z + pgx.z;
            float go = s.w + pgx.w;
            float si = 1.f / (1.f + expf(-gi));
            float sf = 1.f / (1.f + expf(-gf));
            float tg = tanhf(gg);
            float so = 1.f / (1.f + expf(-go));
            float c = sf * sC[tid] + si * tg;
            sC[tid] = c;
            float h = so * tanhf(c);
            g_hbuf[t & 1][bb * 512 + jcol] = h;
            g_hs[((size_t)t * 32 + bb) * 512 + jcol] = h;
        }
        __threadfence();

        if (t + 1 < T1 && tid < 128) {   // prefetch next step's gx
            size_t gxb = ((size_t)(t + 1) * 32 + bb) * GD + jcol;
            pgx.x = __ldg(&g_gx[gxb +    0]);
            pgx.y = __ldg(&g_gx[gxb +  512]);
            pgx.z = __ldg(&g_gx[gxb + 1024]);
            pgx.w = __ldg(&g_gx[gxb + 1536]);
        }
    }
}

// ---------------------------------------------------------------------------
// Logits GEMM via single-pass fp16 mma.sync + per-tile row max.
// ---------------------------------------------------------------------------
#define ISSUE_CHUNK(ch) do { \
    int _buf = (ch) & 1; int _k0 = (ch) * 32; \
    _Pragma("unroll") \
    for (int _it = 0; _it < 2; _it++) { \
        int _idx = tid + _it * 256; \
        int _r = _idx >> 2, _c8 = (_idx & 3) * 8; \
        int _gm = m0 + _r; \
        const __half* _srcA = g_hsh + (size_t)(_gm < MR ? _gm : 0) * HH + _k0 + _c8; \
        uint32_t _dstA = sAu + _buf * LBUFB + (_r * SAP + _c8) * 2; \
        int _szA = (_gm < MR) ? 16 : 0; \
        asm volatile("cp.async.cg.shared.global [%0], [%1], 16, %2;\n" \
                     :: "r"(_dstA), "l"(_srcA), "r"(_szA)); \
        const __half* _srcB = g_wh + (size_t)(n0 + _r) * HH + _k0 + _c8; \
        uint32_t _dstB = sBu + _buf * LBUFB + (_r * SAP + _c8) * 2; \
        asm volatile("cp.async.cg.shared.global [%0], [%1], 16;\n" \
                     :: "r"(_dstB), "l"(_srcB)); \
    } \
    asm volatile("cp.async.commit_group;\n"); \
} while (0)

__global__ __launch_bounds__(256) void gemm_logits_f16(
    const float* __restrict__ bias, float* __restrict__ out)
{
    __shared__ __half sA[2][128 * SAP];
    __shared__ __half sB[2][128 * SAP];
    __shared__ float sbias[128];
    __shared__ unsigned srmax[128];

    const int tid = threadIdx.x, lane = tid & 31, wid = tid >> 5;
    const int m0 = blockIdx.x * 128, n0 = blockIdx.y * 128;
    const int wm = (wid & 1) * 64, wn = (wid >> 1) * 32;
    const uint32_t LBUFB = 128 * SAP * 2;

    if (tid < 128) { sbias[tid] = bias[n0 + tid]; srmax[tid] = 0u; }

    const uint32_t sAu = smem_u32(sA);
    const uint32_t sBu = smem_u32(sB);

    const int rowA = lane & 15;
    const int kA   = (lane >> 4) << 3;
    const int rowB = (lane & 7) + ((lane >> 4) << 3);
    const int kB   = (lane & 8) ? 8 : 0;

    float c[4][4][4];
#pragma unroll
    for (int mi = 0; mi < 4; mi++)
#pragma unroll
        for (int ni = 0; ni < 4; ni++)
#pragma unroll
            for (int q = 0; q < 4; q++) c[mi][ni][q] = 0.f;

    ISSUE_CHUNK(0);

    for (int ch = 0; ch < 16; ch++) {
        const int buf = ch & 1;
        if (ch < 15) {
            ISSUE_CHUNK(ch + 1);
            asm volatile("cp.async.wait_group 1;\n");
        } else {
            asm volatile("cp.async.wait_group 0;\n");
        }
        __syncthreads();

#pragma unroll
        for (int kk = 0; kk < 32; kk += 16) {
            uint32_t aF[4][4], bF[4][2];
#pragma unroll
            for (int mi = 0; mi < 4; mi++) {
                uint32_t ad = sAu + buf * LBUFB +
                    (uint32_t)((wm + mi * 16 + rowA) * SAP + kk + kA) * 2;
                LDMX4(aF[mi], ad);
            }
#pragma unroll
            for (int nb = 0; nb < 2; nb++) {
                uint32_t r4[4];
                uint32_t bd = sBu + buf * LBUFB +
                    (uint32_t)((wn + nb * 16 + rowB) * SAP + kk + kB) * 2;
                LDMX4(r4, bd);
                bF[2 * nb][0] = r4[0]; bF[2 * nb][1] = r4[1];
                bF[2 * nb + 1][0] = r4[2]; bF[2 * nb + 1][1] = r4[3];
            }
#pragma unroll
            for (int mi = 0; mi < 4; mi++)
#pragma unroll
                for (int ni = 0; ni < 4; ni++)
                    MMA16816F(c[mi][ni], aF[mi], bF[ni][0], bF[ni][1]);
        }
        __syncthreads();
    }

    const int erow = lane >> 2;
    const int ecol = (lane & 3) * 2;
#pragma unroll
    for (int mi = 0; mi < 4; mi++) {
#pragma unroll
        for (int half = 0; half < 2; half++) {
            int mrow = wm + mi * 16 + erow + half * 8;
            int gm = m0 + mrow;
            if (gm < MR) {
                int tt = gm >> 5, b = gm & 31;
                float* dst = out + (size_t)(b * 63 + tt) * VV + n0 + wn;
                float mx = -INFINITY;
#pragma unroll
                for (int ni = 0; ni < 4; ni++) {
                    float2 o;
                    o.x = c[mi][ni][half * 2 + 0] + sbias[wn + ni * 8 + ecol + 0];
                    o.y = c[mi][ni][half * 2 + 1] + sbias[wn + ni * 8 + ecol + 1];
                    *(float2*)(dst + ni * 8 + ecol) = o;
                    mx = fmaxf(mx, fmaxf(o.x, o.y));
                }
                atomicMax(&srmax[mrow], fkey(mx));
            }
        }
    }
    __syncthreads();
    if (tid < 128) {
        int gm = m0 + tid;
        if (gm < MR) {
            int tt = gm >> 5, b = gm & 31;
            g_tmax[(size_t)(b * 63 + tt) * NTB + blockIdx.y] = srmax[tid];
        }
    }
}

// ---------------------------------------------------------------------------
// Rescue: amax from g_tmax (2MB), candidates within DELTA, exact fp32 redo.
// ---------------------------------------------------------------------------
#define DELTA 0.01f
__global__ void rowmax_rescue(const float* __restrict__ logits,
                              const float* __restrict__ Wout,
                              const float* __restrict__ bout,
                              float* __restrict__ probs, float* __restrict__ pred)
{
    const int r = blockIdx.x;
    const int tid = threadIdx.x, lane = tid & 31, wid = tid >> 5;
    const float* row = logits + (size_t)r * VV;

    __shared__ unsigned skey[256];
    unsigned mk = 0u;
    for (int v = tid; v < NTB; v += 256) mk = max(mk, g_tmax[(size_t)r * NTB + v]);
    skey[tid] = mk;
    __syncthreads();
    for (int s = 128; s > 0; s >>= 1) {
        if (tid < s) skey[tid] = max(skey[tid], skey[tid + s]);
        __syncthreads();
    }
    const float amax = keyf(skey[0]);
    __syncthreads();

    __shared__ int cnt;
    __shared__ int cidx[128];
    __shared__ float cval[128];
    if (tid == 0) cnt = 0;
    __syncthreads();
    for (int v = tid; v < VV; v += 256) {
        if (row[v] > amax - DELTA) {
            int p = atomicAdd(&cnt, 1);
            if (p < 128) cidx[p] = v;
        }
    }
    __syncthreads();
    const int n = min(cnt, 128);

    const int b = r / 63, t = r % 63;
    const float* h = g_hs + ((size_t)t * 32 + b) * HH;

    for (int ci = wid; ci < n; ci += 8) {
        const float* w = Wout + (size_t)cidx[ci] * HH;
        float s = 0.f;
        const int kb = lane * 16;
#pragma unroll
        for (int j = 0; j < 4; j++) {
            float4 hv = *(const float4*)(h + kb + j * 4);
            float4 wv = __ldg((const float4*)(w + kb + j * 4));
            s += hv.x * wv.x + hv.y * wv.y + hv.z * wv.z + hv.w * wv.w;
        }
#pragma unroll
        for (int off = 16; off > 0; off >>= 1)
            s += __shfl_xor_sync(0xFFFFFFFF, s, off);
        if (lane == 0) cval[ci] = s + __ldg(bout + cidx[ci]);
    }
    __syncthreads();

    if (tid == 0) {
        float bv = -INFINITY; int bi = VV;
        for (int i = 0; i < n; i++) {
            float v = cval[i]; int ix = cidx[i];
            if (v > bv || (v == bv && ix < bi)) { bv = v; bi = ix; }
        }
        probs[r] = bv;
        pred[r] = (float)bi;
    }
}

// ---------------------------------------------------------------------------
extern "C" void kernel_launch(void* const* d_in, const int* in_sizes, int n_in,
                              void* d_out, int out_size)
{
    const float* enc  = (const float*)d_in[0];
    const int*   cap  = (const int*)  d_in[1];
    const float* emb  = (const float*)d_in[2];
    const float* Wih  = (const float*)d_in[3];
    const float* Whh  = (const float*)d_in[4];
    const float* bih  = (const float*)d_in[5];
    const float* bhh  = (const float*)d_in[6];
    const float* Wout = (const float*)d_in[7];
    const float* bout = (const float*)d_in[8];
    float* out = (float*)d_out;

    cudaFuncSetAttribute(lstm_persist,
                         cudaFuncAttributeMaxDynamicSharedMemorySize, SMEM_BYTES);
    cudaFuncSetAttribute(gemm_gx_f16,
                         cudaFuncAttributeMaxDynamicSharedMemorySize, GX_SMEM);

    init_kernel<<<1, 32>>>();
    convert_w<<<16000, 256>>>(Wout);
    convert_wih<<<2048, 256>>>(Wih);
    build_xs<<<2016, 256>>>(enc, cap, emb);
    gemm_gx_f16<<<dim3(16, 16), 256, GX_SMEM>>>(bih, bhh);
    lstm_persist<<<NCTA, 512, SMEM_BYTES>>>(Whh);
    convert_hs<<<1008, 256>>>();
    gemm_logits_f16<<<dim3(16, NTB), 256>>>(bout, out);

    const long logits_elems = (long)BB * T1 * VV;
    if ((long)out_size >= logits_elems + 2L * BB * T1) {
        rowmax_rescue<<<MR, 256>>>(out, Wout, bout,
                                   out + logits_elems,
                                   out + logits_elems + (long)BB * T1);
    }
}

// round 8
// speedup vs baseline: 4.1107x; 1.2545x over previous
#include <cuda_runtime.h>
#include <cuda_bf16.h>
#include <cuda_fp16.h>
#include <math.h>
#include <stdint.h>

// Problem dims
#define T1 63
#define BB 32
#define HH 512
#define VV 32000
#define MR (T1*BB)       // 2016
#define GD (4*HH)        // 2048
#define KX 1024          // xs K-dim
#define NTB 250          // logits n-blocks

// Scratch (device globals)
__device__ float g_gx[(size_t)MR * GD];
__device__ float g_hs[(size_t)MR * HH];
__device__ unsigned g_bar;
__device__ __half g_wh[(size_t)VV * HH];      // W_out fp16
__device__ __half g_hsh[(size_t)MR * HH];     // h states fp16 (hi)
__device__ __half g_wih_h[(size_t)GD * KX];   // W_ih hi
__device__ __half g_wih_l[(size_t)GD * KX];   // W_ih lo
__device__ __half g_xs_h[(size_t)MR * KX];    // xs hi
__device__ __half g_xs_l[(size_t)MR * KX];    // xs lo
__device__ __half g_hbh[2][BB * HH];          // h double-buffer hi
__device__ __half g_hbl[2][BB * HH];          // h double-buffer lo
__device__ unsigned g_tmax[(size_t)MR * NTB]; // per-(row, nblock) max key

#define NCTA 128
// lstm smem (halves stride 520 => 1040B rows, LDSM conflict-free)
#define SHP 520
#define SREDP 18
#define LSTM_SMEM_BYTES ((32+32+16+16)*SHP*2 + 8*32*SREDP*4 + 128*4)  // 118,784

__device__ __forceinline__ uint32_t smem_u32(const void* p) {
    uint32_t a;
    asm("{ .reg .u64 t; cvta.to.shared.u64 t, %1; cvt.u32.u64 %0, t; }"
        : "=r"(a) : "l"(p));
    return a;
}
__device__ __forceinline__ unsigned fkey(float x) {
    unsigned u = __float_as_uint(x);
    return (u & 0x80000000u) ? ~u : (u | 0x80000000u);
}
__device__ __forceinline__ float keyf(unsigned k) {
    unsigned u = (k & 0x80000000u) ? (k & 0x7FFFFFFFu) : ~k;
    return __uint_as_float(u);
}

#define LDMX4(R, addr) \
    asm volatile("ldmatrix.sync.aligned.m8n8.x4.shared.b16 {%0,%1,%2,%3}, [%4];" \
        : "=r"((R)[0]), "=r"((R)[1]), "=r"((R)[2]), "=r"((R)[3]) : "r"(addr))

#define MMA16816F(C, A, B0, B1) \
    asm volatile("mma.sync.aligned.m16n8k16.row.col.f32.f16.f16.f32 " \
        "{%0,%1,%2,%3}, {%4,%5,%6,%7}, {%8,%9}, {%0,%1,%2,%3};" \
        : "+f"((C)[0]), "+f"((C)[1]), "+f"((C)[2]), "+f"((C)[3]) \
        : "r"((A)[0]), "r"((A)[1]), "r"((A)[2]), "r"((A)[3]), "r"(B0), "r"(B1))

// ---------------------------------------------------------------------------
__global__ void init_kernel() {
    if (threadIdx.x == 0 && blockIdx.x == 0) g_bar = 0u;
}

// ---------------------------------------------------------------------------
// Converters
// ---------------------------------------------------------------------------
__device__ __forceinline__ void split16(float x, __half& h, __half& l) {
    h = __float2half_rn(x);
    l = __float2half_rn(x - __half2float(h));
}
__global__ void convert_w(const float* __restrict__ W) {
    size_t i = ((size_t)blockIdx.x * 256 + threadIdx.x) * 4;
    float4 v = *(const float4*)(W + i);
    __half2 a = __floats2half2_rn(v.x, v.y);
    __half2 b = __floats2half2_rn(v.z, v.w);
    uint2 o; o.x = *(uint32_t*)&a; o.y = *(uint32_t*)&b;
    *(uint2*)(g_wh + i) = o;
}
__global__ void convert_wih(const float* __restrict__ W) {
    size_t i = ((size_t)blockIdx.x * 256 + threadIdx.x) * 4;
    float4 v = *(const float4*)(W + i);
    __half h0, l0, h1, l1, h2, l2, h3, l3;
    split16(v.x, h0, l0); split16(v.y, h1, l1);
    split16(v.z, h2, l2); split16(v.w, h3, l3);
    __half2 ha = __halves2half2(h0, h1), hb = __halves2half2(h2, h3);
    __half2 la = __halves2half2(l0, l1), lb = __halves2half2(l2, l3);
    uint2 oh, ol;
    oh.x = *(uint32_t*)&ha; oh.y = *(uint32_t*)&hb;
    ol.x = *(uint32_t*)&la; ol.y = *(uint32_t*)&lb;
    *(uint2*)(g_wih_h + i) = oh;
    *(uint2*)(g_wih_l + i) = ol;
}
__global__ void build_xs(const float* __restrict__ enc, const int* __restrict__ cap,
                         const float* __restrict__ emb) {
    int i4 = blockIdx.x * 256 + threadIdx.x;
    int m = i4 >> 8;
    int c4 = i4 & 255;
    int k = c4 * 4;
    int tt = m >> 5, b = m & 31;
    const float* src = (k < 512)
        ? (enc + b * 512 + k)
        : (emb + (size_t)__ldg(cap + b * 64 + tt) * 512 + (k - 512));
    float4 v = *(const float4*)src;
    __half h0, l0, h1, l1, h2, l2, h3, l3;
    split16(v.x, h0, l0); split16(v.y, h1, l1);
    split16(v.z, h2, l2); split16(v.w, h3, l3);
    __half2 ha = __halves2half2(h0, h1), hb = __halves2half2(h2, h3);
    __half2 la = __halves2half2(l0, l1), lb = __halves2half2(l2, l3);
    uint2 oh, ol;
    oh.x = *(uint32_t*)&ha; oh.y = *(uint32_t*)&hb;
    ol.x = *(uint32_t*)&la; ol.y = *(uint32_t*)&lb;
    size_t off = (size_t)m * KX + k;
    *(uint2*)(g_xs_h + off) = oh;
    *(uint2*)(g_xs_l + off) = ol;
}

// ---------------------------------------------------------------------------
// gx GEMM via fp16x2-split mma.sync (unchanged from R7)
// ---------------------------------------------------------------------------
#define SAP 40
#define TILEB (128 * SAP * 2)
#define BUFB  (2 * TILEB)
#define AB_REGION (2 * BUFB)
#define GX_SMEM (2 * AB_REGION + 512)

#define GX_ISSUE(ch) do { \
    int _buf = (ch) & 1; int _k0 = (ch) * 32; \
    _Pragma("unroll") \
    for (int _it = 0; _it < 8; _it++) { \
        const int _sel = _it >> 1; \
        int _rem = tid + (_it & 1) * 256; \
        int _r = _rem >> 2, _c8 = (_rem & 3) * 8; \
        uint32_t _dst = (_sel < 2 ? sAu : sBu) + _buf * BUFB \
                      + (_sel & 1) * TILEB + (uint32_t)(_r * SAP + _c8) * 2; \
        if (_sel < 2) { \
            int _gm = m0 + _r; \
            const __half* _src = (_sel == 0 ? g_xs_h : g_xs_l) \
                + (size_t)(_gm < MR ? _gm : 0) * KX + _k0 + _c8; \
            int _sz = (_gm < MR) ? 16 : 0; \
            asm volatile("cp.async.cg.shared.global [%0], [%1], 16, %2;\n" \
                         :: "r"(_dst), "l"(_src), "r"(_sz)); \
        } else { \
            const __half* _src = (_sel == 2 ? g_wih_h : g_wih_l) \
                + (size_t)(n0 + _r) * KX + _k0 + _c8; \
            asm volatile("cp.async.cg.shared.global [%0], [%1], 16;\n" \
                         :: "r"(_dst), "l"(_src)); \
        } \
    } \
    asm volatile("cp.async.commit_group;\n"); \
} while (0)

__global__ __launch_bounds__(256) void gemm_gx_f16(
    const float* __restrict__ bih, const float* __restrict__ bhh)
{
    extern __shared__ char dyn[];
    const uint32_t sAu = smem_u32(dyn);
    const uint32_t sBu = sAu + AB_REGION;
    float* sbias = (float*)(dyn + 2 * AB_REGION);

    const int tid = threadIdx.x, lane = tid & 31, wid = tid >> 5;
    const int m0 = blockIdx.x * 128, n0 = blockIdx.y * 128;
    const int wm = (wid & 1) * 64, wn = (wid >> 1) * 32;

    if (tid < 128) sbias[tid] = bih[n0 + tid] + bhh[n0 + tid];

    const int rowA = lane & 15;
    const int kA   = (lane >> 4) << 3;
    const int rowB = (lane & 7) + ((lane >> 4) << 3);
    const int kB   = (lane & 8) ? 8 : 0;

    float c[4][4][4];
#pragma unroll
    for (int mi = 0; mi < 4; mi++)
#pragma unroll
        for (int ni = 0; ni < 4; ni++)
#pragma unroll
            for (int q = 0; q < 4; q++) c[mi][ni][q] = 0.f;

    GX_ISSUE(0);

    for (int ch = 0; ch < 32; ch++) {
        const int buf = ch & 1;
        if (ch < 31) {
            GX_ISSUE(ch + 1);
            asm volatile("cp.async.wait_group 1;\n");
        } else {
            asm volatile("cp.async.wait_group 0;\n");
        }
        __syncthreads();

#pragma unroll
        for (int kk = 0; kk < 32; kk += 16) {
            uint32_t aH[4][4], aL[4][4], bH[4][2], bL[4][2];
#pragma unroll
            for (int mi = 0; mi < 4; mi++) {
                uint32_t base = sAu + buf * BUFB +
                    (uint32_t)((wm + mi * 16 + rowA) * SAP + kk + kA) * 2;
                LDMX4(aH[mi], base);
                LDMX4(aL[mi], base + TILEB);
            }
#pragma unroll
            for (int nb = 0; nb < 2; nb++) {
                uint32_t base = sBu + buf * BUFB +
                    (uint32_t)((wn + nb * 16 + rowB) * SAP + kk + kB) * 2;
                uint32_t r4[4];
                LDMX4(r4, base);
                bH[2 * nb][0] = r4[0]; bH[2 * nb][1] = r4[1];
                bH[2 * nb + 1][0] = r4[2]; bH[2 * nb + 1][1] = r4[3];
                LDMX4(r4, base + TILEB);
                bL[2 * nb][0] = r4[0]; bL[2 * nb][1] = r4[1];
                bL[2 * nb + 1][0] = r4[2]; bL[2 * nb + 1][1] = r4[3];
            }
#pragma unroll
            for (int mi = 0; mi < 4; mi++)
#pragma unroll
                for (int ni = 0; ni < 4; ni++) {
                    MMA16816F(c[mi][ni], aH[mi], bH[ni][0], bH[ni][1]);
                    MMA16816F(c[mi][ni], aH[mi], bL[ni][0], bL[ni][1]);
                    MMA16816F(c[mi][ni], aL[mi], bH[ni][0], bH[ni][1]);
                }
        }
        __syncthreads();
    }

    const int erow = lane >> 2;
    const int ecol = (lane & 3) * 2;
#pragma unroll
    for (int mi = 0; mi < 4; mi++) {
#pragma unroll
        for (int half = 0; half < 2; half++) {
            int gm = m0 + wm + mi * 16 + erow + half * 8;
            if (gm < MR) {
                float* dst = g_gx + (size_t)gm * GD + n0 + wn;
#pragma unroll
                for (int ni = 0; ni < 4; ni++) {
                    float2 o;
                    o.x = c[mi][ni][half * 2 + 0] + sbias[wn + ni * 8 + ecol + 0];
                    o.y = c[mi][ni][half * 2 + 1] + sbias[wn + ni * 8 + ecol + 1];
                    *(float2*)(dst + ni * 8 + ecol) = o;
                }
            }
        }
    }
}

// ---------------------------------------------------------------------------
// Persistent LSTM w/ tensor-core recurrence. 128 CTAs x 512 threads.
// CTA owns 16 gate rows (row = g*4 + jl, gate row g*512 + j0 + jl).
// S[32x16] = h[32x512] @ Wslice[16x512]^T via m16n8k16 fp16x2-split (3 MMA).
// Warp w: m-tile = w&1, k-oct = w>>1 (4 k-tiles of 16). W frags in registers.
// ---------------------------------------------------------------------------
__device__ __forceinline__ void grid_barrier(unsigned target) {
    __syncthreads();
    if (threadIdx.x == 0) {
        unsigned a = atomicAdd(&g_bar, 1u) + 1u;
        if (a < target) {
            while (*(volatile unsigned*)&g_bar < target) { }
        }
    }
    __syncthreads();
}

__global__ __launch_bounds__(512, 1) void lstm_persist(const float* __restrict__ Whh)
{
    extern __shared__ char dsm[];
    __half* sHh = (__half*)dsm;                 // [32][SHP]
    __half* sHl = sHh + 32 * SHP;               // [32][SHP]
    __half* sWh = sHl + 32 * SHP;               // [16][SHP]
    __half* sWl = sWh + 16 * SHP;               // [16][SHP]
    float*  sRed = (float*)(sWl + 16 * SHP);    // [8][32][SREDP]
    float*  sC   = sRed + 8 * 32 * SREDP;       // [128]

    const int tid = threadIdx.x, lane = tid & 31, wid = tid >> 5;
    const int j0 = blockIdx.x * 4;

    // Stage W_hh slice as fp16 hi/lo (once).
    for (int i = tid; i < 16 * 128; i += 512) {   // float4 units
        int row = i >> 7, c4 = i & 127;
        int g = row >> 2, j = row & 3;
        float4 v = *(const float4*)(Whh + (size_t)(g * 512 + j0 + j) * 512 + c4 * 4);
        __half h0, l0, h1, l1, h2, l2, h3, l3;
        split16(v.x, h0, l0); split16(v.y, h1, l1);
        split16(v.z, h2, l2); split16(v.w, h3, l3);
        __half2 ha = __halves2half2(h0, h1), hb = __halves2half2(h2, h3);
        __half2 la = __halves2half2(l0, l1), lb = __halves2half2(l2, l3);
        uint2 oh, ol;
        oh.x = *(uint32_t*)&ha; oh.y = *(uint32_t*)&hb;
        ol.x = *(uint32_t*)&la; ol.y = *(uint32_t*)&lb;
        *(uint2*)(sWh + row * SHP + c4 * 4) = oh;
        *(uint2*)(sWl + row * SHP + c4 * 4) = ol;
    }
    if (tid < 128) sC[tid] = 0.f;
    __syncthreads();

    // Pre-load B (W) fragments into registers.
    const int mt = wid & 1, koct = wid >> 1;
    const int rowB = (lane & 7) + ((lane >> 4) << 3);
    const int kB   = (lane & 8) ? 8 : 0;
    const int rowA = lane & 15;
    const int kA   = (lane >> 4) << 3;
    const uint32_t sWhu = smem_u32(sWh), sWlu = smem_u32(sWl);
    const uint32_t sHhu = smem_u32(sHh), sHlu = smem_u32(sHl);

    uint32_t bH[4][2][2], bL[4][2][2];
#pragma unroll
    for (int kt = 0; kt < 4; kt++) {
        int kk = (koct * 4 + kt) * 16;
        uint32_t r4[4];
        LDMX4(r4, sWhu + (uint32_t)(rowB * SHP + kk + kB) * 2);
        bH[kt][0][0] = r4[0]; bH[kt][0][1] = r4[1];
        bH[kt][1][0] = r4[2]; bH[kt][1][1] = r4[3];
        LDMX4(r4, sWlu + (uint32_t)(rowB * SHP + kk + kB) * 2);
        bL[kt][0][0] = r4[0]; bL[kt][0][1] = r4[1];
        bL[kt][1][0] = r4[2]; bL[kt][1][1] = r4[3];
    }

    const int bb = tid >> 2, jl = tid & 3;
    const int jcol = j0 + jl;

    // step 0: h = 0 -> gates = gx only
    if (tid < 128) {
        size_t gxb = (size_t)bb * GD + jcol;
        float gi = g_gx[gxb +    0];
        float gg = g_gx[gxb + 1024];
        float go = g_gx[gxb + 1536];
        float si = 1.f / (1.f + expf(-gi));
        float tg = tanhf(gg);
        float so = 1.f / (1.f + expf(-go));
        float c = si * tg;
        sC[tid] = c;
        float h = so * tanhf(c);
        __half hh, hl;
        split16(h, hh, hl);
        g_hs[(size_t)bb * 512 + jcol] = h;
        g_hsh[(size_t)bb * 512 + jcol] = hh;
        g_hbh[0][bb * 512 + jcol] = hh;
        g_hbl[0][bb * 512 + jcol] = hl;
    }
    __threadfence();

    // prefetch gx for t=1
    float4 pgx = make_float4(0.f, 0.f, 0.f, 0.f);
    if (tid < 128) {
        size_t gxb = ((size_t)32 + bb) * GD + jcol;
        pgx.x = __ldg(&g_gx[gxb +    0]);
        pgx.y = __ldg(&g_gx[gxb +  512]);
        pgx.z = __ldg(&g_gx[gxb + 1024]);
        pgx.w = __ldg(&g_gx[gxb + 1536]);
    }

    for (int t = 1; t < T1; t++) {
        grid_barrier((unsigned)NCTA * (unsigned)t);

        // stage h hi/lo planes into smem (L2-coherent)
        {
            const __half* srcH = g_hbh[(t - 1) & 1];
            const __half* srcL = g_hbl[(t - 1) & 1];
#pragma unroll
            for (int it = 0; it < 8; it++) {
                int u = tid + it * 512;           // 16B chunk index, 2 planes
                int plane = u >> 11;
                int rem = u & 2047;
                int row = rem >> 6, c16 = rem & 63;
                const __half* src = (plane ? srcL : srcH) + row * 512 + c16 * 8;
                uint4 v = __ldcg((const uint4*)src);
                __half* d = (plane ? sHl : sHh) + row * SHP + c16 * 8;
                *(uint4*)d = v;
            }
        }
        __syncthreads();

        // MMA: c[nt][4] accumulates over this warp's 4 k-tiles, 3 splits
        float c0[4] = {0.f, 0.f, 0.f, 0.f};
        float c1[4] = {0.f, 0.f, 0.f, 0.f};
#pragma unroll
        for (int kt = 0; kt < 4; kt++) {
            int kk = (koct * 4 + kt) * 16;
            uint32_t aH[4], aL[4];
            uint32_t ad = (uint32_t)((mt * 16 + rowA) * SHP + kk + kA) * 2;
            LDMX4(aH, sHhu + ad);
            LDMX4(aL, sHlu + ad);
            MMA16816F(c0, aH, bH[kt][0][0], bH[kt][0][1]);
            MMA16816F(c0, aH, bL[kt][0][0], bL[kt][0][1]);
            MMA16816F(c0, aL, bH[kt][0][0], bH[kt][0][1]);
            MMA16816F(c1, aH, bH[kt][1][0], bH[kt][1][1]);
            MMA16816F(c1, aH, bL[kt][1][0], bL[kt][1][1]);
            MMA16816F(c1, aL, bH[kt][1][0], bH[kt][1][1]);
        }
        // store partials: sRed[koct][b][n]
        {
            int r = lane >> 2, cc = (lane & 3) * 2;
            int b0 = mt * 16 + r, b1 = b0 + 8;
            float* p0 = sRed + (koct * 32 + b0) * SREDP;
            float* p1 = sRed + (koct * 32 + b1) * SREDP;
            *(float2*)(p0 + cc)     = make_float2(c0[0], c0[1]);
            *(float2*)(p1 + cc)     = make_float2(c0[2], c0[3]);
            *(float2*)(p0 + 8 + cc) = make_float2(c1[0], c1[1]);
            *(float2*)(p1 + 8 + cc) = make_float2(c1[2], c1[3]);
        }
        __syncthreads();

        if (tid < 128) {
            float s0 = 0.f, s1 = 0.f, s2 = 0.f, s3 = 0.f;
#pragma unroll
            for (int ko = 0; ko < 8; ko++) {
                const float* p = sRed + (ko * 32 + bb) * SREDP + jl;
                s0 += p[0]; s1 += p[4]; s2 += p[8]; s3 += p[12];
            }
            float gi = s0 + pgx.x;
            float gf = s1 + pgx.y;
            float gg = s2 + pgx.z;
            float go = s3 + pgx.w;
            float si = 1.f / (1.f + expf(-gi));
            float sf = 1.f / (1.f + expf(-gf));
            float tg = tanhf(gg);
            float so = 1.f / (1.f + expf(-go));
            float c = sf * sC[tid] + si * tg;
            sC[tid] = c;
            float h = so * tanhf(c);
            __half hh, hl;
            split16(h, hh, hl);
            g_hs[((size_t)t * 32 + bb) * 512 + jcol] = h;
            g_hsh[((size_t)t * 32 + bb) * 512 + jcol] = hh;
            g_hbh[t & 1][bb * 512 + jcol] = hh;
            g_hbl[t & 1][bb * 512 + jcol] = hl;
        }
        __threadfence();

        if (t + 1 < T1 && tid < 128) {
            size_t gxb = ((size_t)(t + 1) * 32 + bb) * GD + jcol;
            pgx.x = __ldg(&g_gx[gxb +    0]);
            pgx.y = __ldg(&g_gx[gxb +  512]);
            pgx.z = __ldg(&g_gx[gxb + 1024]);
            pgx.w = __ldg(&g_gx[gxb + 1536]);
        }
    }
}

// ---------------------------------------------------------------------------
// Logits GEMM via single-pass fp16 mma.sync + per-tile row max (unchanged)
// ---------------------------------------------------------------------------
#define ISSUE_CHUNK(ch) do { \
    int _buf = (ch) & 1; int _k0 = (ch) * 32; \
    _Pragma("unroll") \
    for (int _it = 0; _it < 2; _it++) { \
        int _idx = tid + _it * 256; \
        int _r = _idx >> 2, _c8 = (_idx & 3) * 8; \
        int _gm = m0 + _r; \
        const __half* _srcA = g_hsh + (size_t)(_gm < MR ? _gm : 0) * HH + _k0 + _c8; \
        uint32_t _dstA = sAu + _buf * LBUFB + (_r * SAP + _c8) * 2; \
        int _szA = (_gm < MR) ? 16 : 0; \
        asm volatile("cp.async.cg.shared.global [%0], [%1], 16, %2;\n" \
                     :: "r"(_dstA), "l"(_srcA), "r"(_szA)); \
        const __half* _srcB = g_wh + (size_t)(n0 + _r) * HH + _k0 + _c8; \
        uint32_t _dstB = sBu + _buf * LBUFB + (_r * SAP + _c8) * 2; \
        asm volatile("cp.async.cg.shared.global [%0], [%1], 16;\n" \
                     :: "r"(_dstB), "l"(_srcB)); \
    } \
    asm volatile("cp.async.commit_group;\n"); \
} while (0)

__global__ __launch_bounds__(256) void gemm_logits_f16(
    const float* __restrict__ bias, float* __restrict__ out)
{
    __shared__ __half sA[2][128 * SAP];
    __shared__ __half sB[2][128 * SAP];
    __shared__ float sbias[128];
    __shared__ unsigned srmax[128];

    const int tid = threadIdx.x, lane = tid & 31, wid = tid >> 5;
    const int m0 = blockIdx.x * 128, n0 = blockIdx.y * 128;
    const int wm = (wid & 1) * 64, wn = (wid >> 1) * 32;
    const uint32_t LBUFB = 128 * SAP * 2;

    if (tid < 128) { sbias[tid] = bias[n0 + tid]; srmax[tid] = 0u; }

    const uint32_t sAu = smem_u32(sA);
    const uint32_t sBu = smem_u32(sB);

    const int rowA = lane & 15;
    const int kA   = (lane >> 4) << 3;
    const int rowB = (lane & 7) + ((lane >> 4) << 3);
    const int kB   = (lane & 8) ? 8 : 0;

    float c[4][4][4];
#pragma unroll
    for (int mi = 0; mi < 4; mi++)
#pragma unroll
        for (int ni = 0; ni < 4; ni++)
#pragma unroll
            for (int q = 0; q < 4; q++) c[mi][ni][q] = 0.f;

    ISSUE_CHUNK(0);

    for (int ch = 0; ch < 16; ch++) {
        const int buf = ch & 1;
        if (ch < 15) {
            ISSUE_CHUNK(ch + 1);
            asm volatile("cp.async.wait_group 1;\n");
        } else {
            asm volatile("cp.async.wait_group 0;\n");
        }
        __syncthreads();

#pragma unroll
        for (int kk = 0; kk < 32; kk += 16) {
            uint32_t aF[4][4], bF[4][2];
#pragma unroll
            for (int mi = 0; mi < 4; mi++) {
                uint32_t ad = sAu + buf * LBUFB +
                    (uint32_t)((wm + mi * 16 + rowA) * SAP + kk + kA) * 2;
                LDMX4(aF[mi], ad);
            }
#pragma unroll
            for (int nb = 0; nb < 2; nb++) {
                uint32_t r4[4];
                uint32_t bd = sBu + buf * LBUFB +
                    (uint32_t)((wn + nb * 16 + rowB) * SAP + kk + kB) * 2;
                LDMX4(r4, bd);
                bF[2 * nb][0] = r4[0]; bF[2 * nb][1] = r4[1];
                bF[2 * nb + 1][0] = r4[2]; bF[2 * nb + 1][1] = r4[3];
            }
#pragma unroll
            for (int mi = 0; mi < 4; mi++)
#pragma unroll
                for (int ni = 0; ni < 4; ni++)
                    MMA16816F(c[mi][ni], aF[mi], bF[ni][0], bF[ni][1]);
        }
        __syncthreads();
    }

    const int erow = lane >> 2;
    const int ecol = (lane & 3) * 2;
#pragma unroll
    for (int mi = 0; mi < 4; mi++) {
#pragma unroll
        for (int half = 0; half < 2; half++) {
            int mrow = wm + mi * 16 + erow + half * 8;
            int gm = m0 + mrow;
            if (gm < MR) {
                int tt = gm >> 5, b = gm & 31;
                float* dst = out + (size_t)(b * 63 + tt) * VV + n0 + wn;
                float mx = -INFINITY;
#pragma unroll
                for (int ni = 0; ni < 4; ni++) {
                    float2 o;
                    o.x = c[mi][ni][half * 2 + 0] + sbias[wn + ni * 8 + ecol + 0];
                    o.y = c[mi][ni][half * 2 + 1] + sbias[wn + ni * 8 + ecol + 1];
                    *(float2*)(dst + ni * 8 + ecol) = o;
                    mx = fmaxf(mx, fmaxf(o.x, o.y));
                }
                atomicMax(&srmax[mrow], fkey(mx));
            }
        }
    }
    __syncthreads();
    if (tid < 128) {
        int gm = m0 + tid;
        if (gm < MR) {
            int tt = gm >> 5, b = gm & 31;
            g_tmax[(size_t)(b * 63 + tt) * NTB + blockIdx.y] = srmax[tid];
        }
    }
}

// ---------------------------------------------------------------------------
// Rescue with block-skip: only scan n-blocks whose tile max qualifies.
// ---------------------------------------------------------------------------
#define DELTA 0.01f
__global__ void rowmax_rescue(const float* __restrict__ logits,
                              const float* __restrict__ Wout,
                              const float* __restrict__ bout,
                              float* __restrict__ probs, float* __restrict__ pred)
{
    const int r = blockIdx.x;
    const int tid = threadIdx.x, lane = tid & 31, wid = tid >> 5;
    const float* row = logits + (size_t)r * VV;

    __shared__ unsigned skey[256];
    unsigned mk = 0u;
    for (int v = tid; v < NTB; v += 256) mk = max(mk, g_tmax[(size_t)r * NTB + v]);
    skey[tid] = mk;
    __syncthreads();
    for (int s = 128; s > 0; s >>= 1) {
        if (tid < s) skey[tid] = max(skey[tid], skey[tid + s]);
        __syncthreads();
    }
    const float amax = keyf(skey[0]);
    const float thresh = amax - DELTA;
    const unsigned tkey = fkey(thresh);
    __syncthreads();

    // qualifying blocks
    __shared__ int qblk[128];
    __shared__ int nq;
    if (tid == 0) nq = 0;
    __syncthreads();
    for (int v = tid; v < NTB; v += 256) {
        if (g_tmax[(size_t)r * NTB + v] > tkey) {
            int p = atomicAdd(&nq, 1);
            if (p < 128) qblk[p] = v;
        }
    }
    __syncthreads();
    const int nqq = min(nq, 128);

    __shared__ int cnt;
    __shared__ int cidx[128];
    __shared__ float cval[128];
    if (tid == 0) cnt = 0;
    __syncthreads();
    for (int q = 0; q < nqq; q++) {
        if (tid < 128) {
            int v = qblk[q] * 128 + tid;
            if (v < VV && row[v] > thresh) {
                int p = atomicAdd(&cnt, 1);
                if (p < 128) cidx[p] = v;
            }
        }
    }
    __syncthreads();
    const int n = min(cnt, 128);

    const int b = r / 63, t = r % 63;
    const float* h = g_hs + ((size_t)t * 32 + b) * HH;

    for (int ci = wid; ci < n; ci += 8) {
        const float* w = Wout + (size_t)cidx[ci] * HH;
        float s = 0.f;
        const int kb = lane * 16;
#pragma unroll
        for (int j = 0; j < 4; j++) {
            float4 hv = *(const float4*)(h + kb + j * 4);
            float4 wv = __ldg((const float4*)(w + kb + j * 4));
            s += hv.x * wv.x + hv.y * wv.y + hv.z * wv.z + hv.w * wv.w;
        }
#pragma unroll
        for (int off = 16; off > 0; off >>= 1)
            s += __shfl_xor_sync(0xFFFFFFFF, s, off);
        if (lane == 0) cval[ci] = s + __ldg(bout + cidx[ci]);
    }
    __syncthreads();

    if (tid == 0) {
        float bv = -INFINITY; int bi = VV;
        for (int i = 0; i < n; i++) {
            float v = cval[i]; int ix = cidx[i];
            if (v > bv || (v == bv && ix < bi)) { bv = v; bi = ix; }
        }
        probs[r] = bv;
        pred[r] = (float)bi;
    }
}

// ---------------------------------------------------------------------------
extern "C" void kernel_launch(void* const* d_in, const int* in_sizes, int n_in,
                              void* d_out, int out_size)
{
    const float* enc  = (const float*)d_in[0];
    const int*   cap  = (const int*)  d_in[1];
    const float* emb  = (const float*)d_in[2];
    const float* Wih  = (const float*)d_in[3];
    const float* Whh  = (const float*)d_in[4];
    const float* bih  = (const float*)d_in[5];
    const float* bhh  = (const float*)d_in[6];
    const float* Wout = (const float*)d_in[7];
    const float* bout = (const float*)d_in[8];
    float* out = (float*)d_out;

    cudaFuncSetAttribute(lstm_persist,
                         cudaFuncAttributeMaxDynamicSharedMemorySize, LSTM_SMEM_BYTES);
    cudaFuncSetAttribute(gemm_gx_f16,
                         cudaFuncAttributeMaxDynamicSharedMemorySize, GX_SMEM);

    init_kernel<<<1, 32>>>();
    convert_w<<<16000, 256>>>(Wout);
    convert_wih<<<2048, 256>>>(Wih);
    build_xs<<<2016, 256>>>(enc, cap, emb);
    gemm_gx_f16<<<dim3(16, 16), 256, GX_SMEM>>>(bih, bhh);
    lstm_persist<<<NCTA, 512, LSTM_SMEM_BYTES>>>(Whh);
    gemm_logits_f16<<<dim3(16, NTB), 256>>>(bout, out);

    const long logits_elems = (long)BB * T1 * VV;
    if ((long)out_size >= logits_elems + 2L * BB * T1) {
        rowmax_rescue<<<MR, 256>>>(out, Wout, bout,
                                   out + logits_elems,
                                   out + logits_elems + (long)BB * T1);
    }
}